// round 1
// baseline (speedup 1.0000x reference)
#include <cuda_runtime.h>

#define NN   50000
#define NF   512
#define NHID 64
#define H1N  8
#define NC   16
#define NE   1600000
#define HID1 512   /* H1N*NHID */

// ---------------- scratch (device globals; no allocations allowed) ----------
__device__ float g_h1 [NN * HID1];   // layer-1 per-head features, [n][head*64+f]
__device__ float g_hp1[NN * HID1];   // layer-1 output (elu'd, concat) = layer-2 input
__device__ float g_ssrc1[H1N * NN];
__device__ float g_sdst1[H1N * NN];
__device__ float g_h2 [NN * NC];
__device__ float g_ss2[NN];
__device__ float g_sd2[NN];
__device__ int   g_deg[NN];
__device__ int   g_rowptr[NN + 1];
__device__ int   g_cursor[NN];
__device__ int   g_col[NE];

// ---------------- CSR construction ----------------
__global__ void zero_deg_kernel() {
    int i = blockIdx.x * blockDim.x + threadIdx.x;
    if (i < NN) g_deg[i] = 0;
}

__global__ void hist_kernel(const int* __restrict__ src, int E) {
    int i = blockIdx.x * blockDim.x + threadIdx.x;
    if (i < E) atomicAdd(&g_deg[src[i]], 1);
}

// single-block scan over 50000 ints (1024 threads, chunked)
__global__ void scan_kernel() {
    __shared__ int warpsums[32];
    __shared__ int s_carry;
    int t = threadIdx.x;
    int lane = t & 31, wid = t >> 5;
    if (t == 0) { s_carry = 0; g_rowptr[0] = 0; }
    __syncthreads();
    for (int base = 0; base < NN; base += 1024) {
        int idx = base + t;
        int v = (idx < NN) ? g_deg[idx] : 0;
        int x = v;
        #pragma unroll
        for (int o = 1; o < 32; o <<= 1) {
            int y = __shfl_up_sync(0xffffffffu, x, o);
            if (lane >= o) x += y;
        }
        if (lane == 31) warpsums[wid] = x;
        __syncthreads();
        if (wid == 0) {
            int w = warpsums[lane];
            #pragma unroll
            for (int o = 1; o < 32; o <<= 1) {
                int y = __shfl_up_sync(0xffffffffu, w, o);
                if (lane >= o) w += y;
            }
            warpsums[lane] = w;
        }
        __syncthreads();
        int warpoff = (wid > 0) ? warpsums[wid - 1] : 0;
        int incl = s_carry + warpoff + x;
        if (idx < NN) g_rowptr[idx + 1] = incl;
        __syncthreads();
        if (t == 1023) s_carry = incl;
        __syncthreads();
    }
}

__global__ void init_cursor_kernel() {
    int i = blockIdx.x * blockDim.x + threadIdx.x;
    if (i < NN) g_cursor[i] = g_rowptr[i];
}

__global__ void scatter_kernel(const int* __restrict__ src,
                               const int* __restrict__ dst, int E) {
    int i = blockIdx.x * blockDim.x + threadIdx.x;
    if (i < E) {
        int p = atomicAdd(&g_cursor[src[i]], 1);
        g_col[p] = dst[i];
    }
}

// ---------------- GEMM1: h1 = x @ concat_heads(W1)  [50000,512]x[512,512] ----
// W1 layout [8,512,64]: element (k, c) at (c>>6)*32768 + k*64 + (c&63)
__global__ __launch_bounds__(256) void gemm1_kernel(const float* __restrict__ X,
                                                    const float* __restrict__ W) {
    __shared__ float As[16][128];   // [k][m]
    __shared__ float Bs[16][128];   // [k][n]
    int tid = threadIdx.x;
    int tx = tid & 15, ty = tid >> 4;
    int bm = blockIdx.x * 128;
    int bn = blockIdx.y * 128;

    float acc[8][8];
    #pragma unroll
    for (int i = 0; i < 8; i++)
        #pragma unroll
        for (int j = 0; j < 8; j++) acc[i][j] = 0.f;

    for (int k0 = 0; k0 < NF; k0 += 16) {
        #pragma unroll
        for (int r = 0; r < 2; r++) {
            int q = r * 256 + tid;          // 0..511
            int row = q >> 2, kp = (q & 3) * 4;
            int grow = bm + row;
            float4 v = make_float4(0.f, 0.f, 0.f, 0.f);
            if (grow < NN)
                v = *(const float4*)(X + (size_t)grow * NF + k0 + kp);
            As[kp + 0][row] = v.x; As[kp + 1][row] = v.y;
            As[kp + 2][row] = v.z; As[kp + 3][row] = v.w;
        }
        #pragma unroll
        for (int r = 0; r < 2; r++) {
            int q = r * 256 + tid;
            int k = q >> 5, c = (q & 31) * 4;
            int cg = bn + c;
            const float* wp = W + (cg >> 6) * (NF * NHID) + (k0 + k) * NHID + (cg & 63);
            *(float4*)&Bs[k][c] = *(const float4*)wp;
        }
        __syncthreads();
        #pragma unroll
        for (int kk = 0; kk < 16; kk++) {
            float4 a0 = *(const float4*)&As[kk][ty * 4];
            float4 a1 = *(const float4*)&As[kk][64 + ty * 4];
            float4 b0 = *(const float4*)&Bs[kk][tx * 4];
            float4 b1 = *(const float4*)&Bs[kk][64 + tx * 4];
            float a[8] = {a0.x, a0.y, a0.z, a0.w, a1.x, a1.y, a1.z, a1.w};
            float b[8] = {b0.x, b0.y, b0.z, b0.w, b1.x, b1.y, b1.z, b1.w};
            #pragma unroll
            for (int i = 0; i < 8; i++)
                #pragma unroll
                for (int j = 0; j < 8; j++) acc[i][j] += a[i] * b[j];
        }
        __syncthreads();
    }
    #pragma unroll
    for (int i = 0; i < 8; i++) {
        int r = bm + ((i < 4) ? (ty * 4 + i) : (64 + ty * 4 + (i - 4)));
        if (r < NN) {
            float* o = g_h1 + (size_t)r * HID1 + bn;
            *(float4*)(o + tx * 4)      = make_float4(acc[i][0], acc[i][1], acc[i][2], acc[i][3]);
            *(float4*)(o + 64 + tx * 4) = make_float4(acc[i][4], acc[i][5], acc[i][6], acc[i][7]);
        }
    }
}

// ---------------- per-node attention scores, layer 1 ----------------
__global__ void s1_kernel(const float* __restrict__ a1) {
    int gw = (blockIdx.x * blockDim.x + threadIdx.x) >> 5;
    int lane = threadIdx.x & 31;
    if (gw >= NN) return;
    const float* hrow = g_h1 + (size_t)gw * HID1;
    #pragma unroll
    for (int h = 0; h < H1N; ++h) {
        float x0 = hrow[h * 64 + lane], x1 = hrow[h * 64 + 32 + lane];
        float vs = x0 * a1[h * 128 + lane]      + x1 * a1[h * 128 + 32 + lane];
        float vd = x0 * a1[h * 128 + 64 + lane] + x1 * a1[h * 128 + 96 + lane];
        #pragma unroll
        for (int o = 16; o; o >>= 1) {
            vs += __shfl_xor_sync(0xffffffffu, vs, o);
            vd += __shfl_xor_sync(0xffffffffu, vd, o);
        }
        if (lane == 0) { g_ssrc1[h * NN + gw] = vs; g_sdst1[h * NN + gw] = vd; }
    }
}

// ---------------- layer-1 edge aggregation (CSR, no atomics) ----------------
// block = node; 128 threads; thread t owns features [t*4, t*4+4) (head = t>>4)
__global__ __launch_bounds__(128) void agg1_kernel() {
    int n = blockIdx.x;
    int t = threadIdx.x;
    int head = t >> 4;
    __shared__ int sc[128];
    int beg = g_rowptr[n], end = g_rowptr[n + 1];
    float ss = g_ssrc1[head * NN + n];
    const float* __restrict__ sdh = g_sdst1 + head * NN;
    float4 acc = make_float4(0.f, 0.f, 0.f, 0.f);
    float rsum = 0.f;
    int c0 = t * 4;
    for (int base = beg; base < end; base += 128) {
        int cnt = min(128, end - base);
        if (t < cnt) sc[t] = g_col[base + t];
        __syncthreads();
        for (int j = 0; j < cnt; j++) {
            int d = sc[j];
            float lg = ss + __ldg(&sdh[d]);
            float lr = lg > 0.f ? lg : 0.2f * lg;
            float ev = __expf(-lr);
            rsum += ev;
            float4 hv = *(const float4*)(g_h1 + (size_t)d * HID1 + c0);
            acc.x += ev * hv.x; acc.y += ev * hv.y;
            acc.z += ev * hv.z; acc.w += ev * hv.w;
        }
        __syncthreads();
    }
    float inv = 1.f / rsum;
    float4 hp = make_float4(acc.x * inv, acc.y * inv, acc.z * inv, acc.w * inv);
    hp.x = hp.x > 0.f ? hp.x : (__expf(hp.x) - 1.f);
    hp.y = hp.y > 0.f ? hp.y : (__expf(hp.y) - 1.f);
    hp.z = hp.z > 0.f ? hp.z : (__expf(hp.z) - 1.f);
    hp.w = hp.w > 0.f ? hp.w : (__expf(hp.w) - 1.f);
    *(float4*)(g_hp1 + (size_t)n * HID1 + c0) = hp;
}

// ---------------- layer-2 GEMM (N=16) + scores ----------------
// 16 threads per node; thread computes one output class
__global__ void l2_kernel(const float* __restrict__ W2, const float* __restrict__ a2) {
    int tid = blockIdx.x * blockDim.x + threadIdx.x;
    int n = tid >> 4, c = tid & 15;
    if (n >= NN) return;
    const float* hrow = g_hp1 + (size_t)n * HID1;
    float acc = 0.f;
    for (int k = 0; k < HID1; k += 4) {
        float4 hv = *(const float4*)(hrow + k);
        acc += hv.x * W2[(k + 0) * NC + c];
        acc += hv.y * W2[(k + 1) * NC + c];
        acc += hv.z * W2[(k + 2) * NC + c];
        acc += hv.w * W2[(k + 3) * NC + c];
    }
    g_h2[n * NC + c] = acc;
    float ps = acc * a2[c], pd = acc * a2[NC + c];
    #pragma unroll
    for (int o = 8; o; o >>= 1) {
        ps += __shfl_xor_sync(0xffffffffu, ps, o, 16);
        pd += __shfl_xor_sync(0xffffffffu, pd, o, 16);
    }
    if (c == 0) { g_ss2[n] = ps; g_sd2[n] = pd; }
}

// ---------------- layer-2 aggregation + elu + log_softmax ----------------
// one warp per node; lanes 0..15 own the 16 classes
__global__ void agg2_kernel(float* __restrict__ out) {
    int gw = (blockIdx.x * blockDim.x + threadIdx.x) >> 5;
    int lane = threadIdx.x & 31;
    if (gw >= NN) return;
    int n = gw;
    int beg = g_rowptr[n], end = g_rowptr[n + 1];
    float ss = g_ss2[n];
    float acc = 0.f, rsum = 0.f;
    for (int base = beg; base < end; base += 32) {
        int cnt = min(32, end - base);
        int d = 0; float ev = 0.f;
        if (lane < cnt) {
            d = g_col[base + lane];
            float lg = ss + g_sd2[d];
            float lr = lg > 0.f ? lg : 0.2f * lg;
            ev = __expf(-lr);
        }
        for (int j = 0; j < cnt; j++) {
            int   dj  = __shfl_sync(0xffffffffu, d, j);
            float evj = __shfl_sync(0xffffffffu, ev, j);
            rsum += evj;
            if (lane < 16) acc += evj * g_h2[dj * NC + lane];
        }
    }
    float v = acc / rsum;                           // h_prime (mean over H2=1)
    float e = v > 0.f ? v : (__expf(v) - 1.f);      // elu
    // log_softmax over 16 lanes
    float m = e;
    #pragma unroll
    for (int o = 8; o; o >>= 1) m = fmaxf(m, __shfl_xor_sync(0xffffffffu, m, o, 16));
    float ex = __expf(e - m);
    float s = ex;
    #pragma unroll
    for (int o = 8; o; o >>= 1) s += __shfl_xor_sync(0xffffffffu, s, o, 16);
    if (lane < 16) out[(size_t)n * NC + lane] = (e - m) - __logf(s);
}

// ---------------- launch ----------------
extern "C" void kernel_launch(void* const* d_in, const int* in_sizes, int n_in,
                              void* d_out, int out_size) {
    const float* x  = (const float*)d_in[0];
    const int*   ei = (const int*)d_in[1];
    const float* W1 = (const float*)d_in[2];
    const float* a1 = (const float*)d_in[3];
    const float* W2 = (const float*)d_in[4];
    const float* a2 = (const float*)d_in[5];
    float* out = (float*)d_out;
    const int E = NE;
    const int* src = ei;
    const int* dst = ei + E;

    // CSR build (shared by both layers)
    zero_deg_kernel<<<(NN + 255) / 256, 256>>>();
    hist_kernel<<<(E + 255) / 256, 256>>>(src, E);
    scan_kernel<<<1, 1024>>>();
    init_cursor_kernel<<<(NN + 255) / 256, 256>>>();
    scatter_kernel<<<(E + 255) / 256, 256>>>(src, dst, E);

    // layer 1
    dim3 g1((NN + 127) / 128, 4);
    gemm1_kernel<<<g1, 256>>>(x, W1);
    s1_kernel<<<(NN * 32 + 255) / 256, 256>>>(a1);
    agg1_kernel<<<NN, 128>>>();

    // layer 2 + output
    l2_kernel<<<(NN * 16 + 255) / 256, 256>>>(W2, a2);
    agg2_kernel<<<(NN * 32 + 255) / 256, 256>>>(out);
}

// round 3
// speedup vs baseline: 2.1238x; 2.1238x over previous
#include <cuda_runtime.h>
#include <cuda_bf16.h>
#include <cstdint>

#define NN    50000
#define NNPAD 50048
#define NF    512
#define NHID  64
#define H1N   8
#define NC    16
#define NE    1600000
#define HID1  512   /* H1N*NHID */

// ---------------- scratch (device globals; no allocations allowed) ----------
__device__ float g_h1 [NN * HID1];
__device__ float g_hp1[NN * HID1];
__device__ float g_ssrc1[H1N * NN];
__device__ float g_sdst1[H1N * NN];
__device__ float g_h2 [NN * NC];
__device__ float g_ss2[NN];
__device__ float g_sd2[NN];
__device__ int   g_deg[NN];
__device__ int   g_rowptr[NN + 1];
__device__ int   g_cursor[NN];
__device__ int   g_col[NE];
// bf16 split operands for tensor-core GEMM1
__device__ __nv_bfloat16 g_Xhi[(size_t)NNPAD * NF];
__device__ __nv_bfloat16 g_Xlo[(size_t)NNPAD * NF];
__device__ __nv_bfloat16 g_Bhi[HID1 * NF];   // [n][k] row-major (n = out feature)
__device__ __nv_bfloat16 g_Blo[HID1 * NF];

// ---------------- helpers ----------------
__device__ __forceinline__ uint32_t smem_u32(const void* p) {
    uint32_t a;
    asm("{ .reg .u64 t; cvta.to.shared.u64 t, %1; cvt.u32.u64 %0, t; }" : "=r"(a) : "l"(p));
    return a;
}
__device__ __forceinline__ void cp_async16(uint32_t dst, const void* src) {
    asm volatile("cp.async.cg.shared.global [%0], [%1], 16;" :: "r"(dst), "l"(src) : "memory");
}
__device__ __forceinline__ void cp_commit() {
    asm volatile("cp.async.commit_group;" ::: "memory");
}
template<int N>
__device__ __forceinline__ void cp_wait() {
    asm volatile("cp.async.wait_group %0;" :: "n"(N) : "memory");
}
__device__ __forceinline__ void ldsm4(uint32_t& r0, uint32_t& r1, uint32_t& r2, uint32_t& r3,
                                      uint32_t addr) {
    asm volatile("ldmatrix.sync.aligned.m8n8.x4.shared.b16 {%0,%1,%2,%3}, [%4];"
                 : "=r"(r0), "=r"(r1), "=r"(r2), "=r"(r3) : "r"(addr));
}
__device__ __forceinline__ void mma16816(float& c0, float& c1, float& c2, float& c3,
                                         uint32_t a0, uint32_t a1, uint32_t a2, uint32_t a3,
                                         uint32_t b0, uint32_t b1) {
    asm volatile("mma.sync.aligned.m16n8k16.row.col.f32.bf16.bf16.f32 "
                 "{%0,%1,%2,%3}, {%4,%5,%6,%7}, {%8,%9}, {%0,%1,%2,%3};"
                 : "+f"(c0), "+f"(c1), "+f"(c2), "+f"(c3)
                 : "r"(a0), "r"(a1), "r"(a2), "r"(a3), "r"(b0), "r"(b1));
}

// ---------------- CSR construction ----------------
__global__ void zero_deg_kernel() {
    int i = blockIdx.x * blockDim.x + threadIdx.x;
    if (i < NN) g_deg[i] = 0;
}
__global__ void hist_kernel(const int* __restrict__ src, int E) {
    int i = blockIdx.x * blockDim.x + threadIdx.x;
    if (i < E) atomicAdd(&g_deg[src[i]], 1);
}
__global__ void scan_kernel() {
    __shared__ int warpsums[32];
    __shared__ int s_carry;
    int t = threadIdx.x;
    int lane = t & 31, wid = t >> 5;
    if (t == 0) { s_carry = 0; g_rowptr[0] = 0; }
    __syncthreads();
    for (int base = 0; base < NN; base += 1024) {
        int idx = base + t;
        int v = (idx < NN) ? g_deg[idx] : 0;
        int x = v;
        #pragma unroll
        for (int o = 1; o < 32; o <<= 1) {
            int y = __shfl_up_sync(0xffffffffu, x, o);
            if (lane >= o) x += y;
        }
        if (lane == 31) warpsums[wid] = x;
        __syncthreads();
        if (wid == 0) {
            int w = warpsums[lane];
            #pragma unroll
            for (int o = 1; o < 32; o <<= 1) {
                int y = __shfl_up_sync(0xffffffffu, w, o);
                if (lane >= o) w += y;
            }
            warpsums[lane] = w;
        }
        __syncthreads();
        int warpoff = (wid > 0) ? warpsums[wid - 1] : 0;
        int incl = s_carry + warpoff + x;
        if (idx < NN) g_rowptr[idx + 1] = incl;
        __syncthreads();
        if (t == 1023) s_carry = incl;
        __syncthreads();
    }
}
__global__ void init_cursor_kernel() {
    int i = blockIdx.x * blockDim.x + threadIdx.x;
    if (i < NN) g_cursor[i] = g_rowptr[i];
}
__global__ void scatter_kernel(const int* __restrict__ src,
                               const int* __restrict__ dst, int E) {
    int i = blockIdx.x * blockDim.x + threadIdx.x;
    if (i < E) {
        int p = atomicAdd(&g_cursor[src[i]], 1);
        g_col[p] = dst[i];
    }
}

// ---------------- fp32 -> split bf16 converters ----------------
__device__ __forceinline__ void split_bf16(float v, __nv_bfloat16& hi, __nv_bfloat16& lo) {
    hi = __float2bfloat16_rn(v);
    lo = __float2bfloat16_rn(v - __bfloat162float(hi));
}
__global__ void convert_x_kernel(const float* __restrict__ X) {
    size_t i = (size_t)blockIdx.x * blockDim.x + threadIdx.x;   // per float4
    if (i >= (size_t)NNPAD * NF / 4) return;
    size_t base = i * 4;
    int row = (int)(base >> 9);
    float4 v = make_float4(0.f, 0.f, 0.f, 0.f);
    if (row < NN) v = *(const float4*)(X + base);
    __nv_bfloat16 h[4], l[4];
    split_bf16(v.x, h[0], l[0]); split_bf16(v.y, h[1], l[1]);
    split_bf16(v.z, h[2], l[2]); split_bf16(v.w, h[3], l[3]);
    uint2 ph, pl;
    ph.x = ((uint32_t)__bfloat16_as_ushort(h[1]) << 16) | __bfloat16_as_ushort(h[0]);
    ph.y = ((uint32_t)__bfloat16_as_ushort(h[3]) << 16) | __bfloat16_as_ushort(h[2]);
    pl.x = ((uint32_t)__bfloat16_as_ushort(l[1]) << 16) | __bfloat16_as_ushort(l[0]);
    pl.y = ((uint32_t)__bfloat16_as_ushort(l[3]) << 16) | __bfloat16_as_ushort(l[2]);
    *(uint2*)(g_Xhi + base) = ph;
    *(uint2*)(g_Xlo + base) = pl;
}
__global__ void convert_w_kernel(const float* __restrict__ W) {
    int tid = blockIdx.x * blockDim.x + threadIdx.x;   // tid = k*512 + n
    if (tid >= HID1 * NF) return;
    int k = tid >> 9, n = tid & 511;
    float w = W[(n >> 6) * (NF * NHID) + k * NHID + (n & 63)];
    __nv_bfloat16 hi, lo;
    split_bf16(w, hi, lo);
    g_Bhi[n * NF + k] = hi;
    g_Blo[n * NF + k] = lo;
}

// ---------------- GEMM1 via mma.sync (HMMA bf16, split) ----------------
// h1[NNPAD,512] = Xsplit @ Bsplit^T.  CTA tile 128x128x32, 8 warps (2x4), warp 64x32.
#define BK 32
#define TSTRIDE 40                         /* bf16 elems per smem row (32 + 8 pad) */
#define TILE_B (128 * TSTRIDE * 2)         /* 10240 bytes per matrix tile */
#define STAGE_B (4 * TILE_B)               /* Ahi,Alo,Bhi,Blo */
#define GEMM_SMEM (2 * STAGE_B)            /* 81920 */

__global__ __launch_bounds__(256, 2) void gemm1_mma_kernel() {
    extern __shared__ char smem[];
    const uint32_t sb = smem_u32(smem);
    const int tid = threadIdx.x;
    const int wid = tid >> 5, lane = tid & 31;
    const int wm = wid >> 2, wn = wid & 3;
    const int bm = blockIdx.x * 128;
    const int bn = blockIdx.y * 128;

    // cp.async loader indices: 2 chunks of 16B per thread per matrix
    const int ldRow0 = tid >> 2;            // 0..63
    const int ldCol  = (tid & 3) * 8;       // bf16 col

    auto load_stage = [&](int s, int buf) {
        const int k0 = s * BK;
        const uint32_t st = sb + buf * STAGE_B;
        #pragma unroll
        for (int i = 0; i < 2; i++) {
            int row = ldRow0 + i * 64;
            uint32_t soff = (row * TSTRIDE + ldCol) * 2;
            cp_async16(st + 0 * TILE_B + soff, g_Xhi + (size_t)(bm + row) * NF + k0 + ldCol);
            cp_async16(st + 1 * TILE_B + soff, g_Xlo + (size_t)(bm + row) * NF + k0 + ldCol);
            cp_async16(st + 2 * TILE_B + soff, g_Bhi + (size_t)(bn + row) * NF + k0 + ldCol);
            cp_async16(st + 3 * TILE_B + soff, g_Blo + (size_t)(bn + row) * NF + k0 + ldCol);
        }
        cp_commit();
    };

    float acc[4][4][4];
    #pragma unroll
    for (int i = 0; i < 4; i++)
        #pragma unroll
        for (int j = 0; j < 4; j++)
            #pragma unroll
            for (int q = 0; q < 4; q++) acc[i][j][q] = 0.f;

    // ldmatrix per-lane selectors
    const uint32_t aRow = lane & 15;
    const uint32_t aCol = (lane & 16) >> 1;                 // 0 or 8
    const uint32_t bRow = (lane & 7) + ((lane & 16) >> 1);  // row within 16-n group
    const uint32_t bCol = (lane & 8) ? 8u : 0u;

    load_stage(0, 0);

    const int NSTAGE = NF / BK;   // 16
    for (int s = 0; s < NSTAGE; s++) {
        const int buf = s & 1;
        if (s + 1 < NSTAGE) {
            load_stage(s + 1, buf ^ 1);
            cp_wait<1>();
        } else {
            cp_wait<0>();
        }
        __syncthreads();

        const uint32_t st = sb + buf * STAGE_B;
        #pragma unroll
        for (int kk = 0; kk < 2; kk++) {
            const int k0 = kk * 16;
            uint32_t ah[4][4], al[4][4], bh[4][2], bl[4][2];
            #pragma unroll
            for (int mt = 0; mt < 4; mt++) {
                uint32_t off = ((wm * 64 + mt * 16 + aRow) * TSTRIDE + k0 + aCol) * 2;
                ldsm4(ah[mt][0], ah[mt][1], ah[mt][2], ah[mt][3], st + 0 * TILE_B + off);
                ldsm4(al[mt][0], al[mt][1], al[mt][2], al[mt][3], st + 1 * TILE_B + off);
            }
            #pragma unroll
            for (int np = 0; np < 2; np++) {   // each x4 covers 2 n-tiles
                uint32_t off = ((wn * 32 + np * 16 + bRow) * TSTRIDE + k0 + bCol) * 2;
                ldsm4(bh[np*2][0], bh[np*2][1], bh[np*2+1][0], bh[np*2+1][1],
                      st + 2 * TILE_B + off);
                ldsm4(bl[np*2][0], bl[np*2][1], bl[np*2+1][0], bl[np*2+1][1],
                      st + 3 * TILE_B + off);
            }
            #pragma unroll
            for (int mt = 0; mt < 4; mt++)
                #pragma unroll
                for (int nt = 0; nt < 4; nt++) {
                    mma16816(acc[mt][nt][0], acc[mt][nt][1], acc[mt][nt][2], acc[mt][nt][3],
                             ah[mt][0], ah[mt][1], ah[mt][2], ah[mt][3], bh[nt][0], bh[nt][1]);
                    mma16816(acc[mt][nt][0], acc[mt][nt][1], acc[mt][nt][2], acc[mt][nt][3],
                             ah[mt][0], ah[mt][1], ah[mt][2], ah[mt][3], bl[nt][0], bl[nt][1]);
                    mma16816(acc[mt][nt][0], acc[mt][nt][1], acc[mt][nt][2], acc[mt][nt][3],
                             al[mt][0], al[mt][1], al[mt][2], al[mt][3], bh[nt][0], bh[nt][1]);
                }
        }
        __syncthreads();
    }

    // epilogue: lane (c0,c1)@(row,col), (c2,c3)@(row+8,col)
    const int erow = (lane >> 2);
    const int ecol = (lane & 3) * 2;
    #pragma unroll
    for (int mt = 0; mt < 4; mt++) {
        int r0 = bm + wm * 64 + mt * 16 + erow;
        #pragma unroll
        for (int nt = 0; nt < 4; nt++) {
            int c = bn + wn * 32 + nt * 8 + ecol;
            if (r0 < NN)
                *(float2*)(g_h1 + (size_t)r0 * HID1 + c) = make_float2(acc[mt][nt][0], acc[mt][nt][1]);
            if (r0 + 8 < NN)
                *(float2*)(g_h1 + (size_t)(r0 + 8) * HID1 + c) = make_float2(acc[mt][nt][2], acc[mt][nt][3]);
        }
    }
}

// ---------------- per-node attention scores, layer 1 ----------------
__global__ void s1_kernel(const float* __restrict__ a1) {
    int gw = (blockIdx.x * blockDim.x + threadIdx.x) >> 5;
    int lane = threadIdx.x & 31;
    if (gw >= NN) return;
    const float* hrow = g_h1 + (size_t)gw * HID1;
    #pragma unroll
    for (int h = 0; h < H1N; ++h) {
        float x0 = hrow[h * 64 + lane], x1 = hrow[h * 64 + 32 + lane];
        float vs = x0 * a1[h * 128 + lane]      + x1 * a1[h * 128 + 32 + lane];
        float vd = x0 * a1[h * 128 + 64 + lane] + x1 * a1[h * 128 + 96 + lane];
        #pragma unroll
        for (int o = 16; o; o >>= 1) {
            vs += __shfl_xor_sync(0xffffffffu, vs, o);
            vd += __shfl_xor_sync(0xffffffffu, vd, o);
        }
        if (lane == 0) { g_ssrc1[h * NN + gw] = vs; g_sdst1[h * NN + gw] = vd; }
    }
}

// ---------------- layer-1 edge aggregation (CSR, no atomics) ----------------
__global__ __launch_bounds__(128) void agg1_kernel() {
    int n = blockIdx.x;
    int t = threadIdx.x;
    int head = t >> 4;
    __shared__ int sc[128];
    int beg = g_rowptr[n], end = g_rowptr[n + 1];
    float ss = g_ssrc1[head * NN + n];
    const float* __restrict__ sdh = g_sdst1 + head * NN;
    float4 acc = make_float4(0.f, 0.f, 0.f, 0.f);
    float rsum = 0.f;
    int c0 = t * 4;
    for (int base = beg; base < end; base += 128) {
        int cnt = min(128, end - base);
        if (t < cnt) sc[t] = g_col[base + t];
        __syncthreads();
        for (int j = 0; j < cnt; j++) {
            int d = sc[j];
            float lg = ss + __ldg(&sdh[d]);
            float lr = lg > 0.f ? lg : 0.2f * lg;
            float ev = __expf(-lr);
            rsum += ev;
            float4 hv = *(const float4*)(g_h1 + (size_t)d * HID1 + c0);
            acc.x += ev * hv.x; acc.y += ev * hv.y;
            acc.z += ev * hv.z; acc.w += ev * hv.w;
        }
        __syncthreads();
    }
    float inv = 1.f / rsum;
    float4 hp = make_float4(acc.x * inv, acc.y * inv, acc.z * inv, acc.w * inv);
    hp.x = hp.x > 0.f ? hp.x : (__expf(hp.x) - 1.f);
    hp.y = hp.y > 0.f ? hp.y : (__expf(hp.y) - 1.f);
    hp.z = hp.z > 0.f ? hp.z : (__expf(hp.z) - 1.f);
    hp.w = hp.w > 0.f ? hp.w : (__expf(hp.w) - 1.f);
    *(float4*)(g_hp1 + (size_t)n * HID1 + c0) = hp;
}

// ---------------- layer-2 GEMM (N=16) + scores ----------------
__global__ void l2_kernel(const float* __restrict__ W2, const float* __restrict__ a2) {
    int tid = blockIdx.x * blockDim.x + threadIdx.x;
    int n = tid >> 4, c = tid & 15;
    if (n >= NN) return;
    const float* hrow = g_hp1 + (size_t)n * HID1;
    float acc = 0.f;
    for (int k = 0; k < HID1; k += 4) {
        float4 hv = *(const float4*)(hrow + k);
        acc += hv.x * W2[(k + 0) * NC + c];
        acc += hv.y * W2[(k + 1) * NC + c];
        acc += hv.z * W2[(k + 2) * NC + c];
        acc += hv.w * W2[(k + 3) * NC + c];
    }
    g_h2[n * NC + c] = acc;
    float ps = acc * a2[c], pd = acc * a2[NC + c];
    #pragma unroll
    for (int o = 8; o; o >>= 1) {
        ps += __shfl_xor_sync(0xffffffffu, ps, o, 16);
        pd += __shfl_xor_sync(0xffffffffu, pd, o, 16);
    }
    if (c == 0) { g_ss2[n] = ps; g_sd2[n] = pd; }
}

// ---------------- layer-2 aggregation + elu + log_softmax ----------------
__global__ void agg2_kernel(float* __restrict__ out) {
    int gw = (blockIdx.x * blockDim.x + threadIdx.x) >> 5;
    int lane = threadIdx.x & 31;
    if (gw >= NN) return;
    int n = gw;
    int beg = g_rowptr[n], end = g_rowptr[n + 1];
    float ss = g_ss2[n];
    float acc = 0.f, rsum = 0.f;
    for (int base = beg; base < end; base += 32) {
        int cnt = min(32, end - base);
        int d = 0; float ev = 0.f;
        if (lane < cnt) {
            d = g_col[base + lane];
            float lg = ss + g_sd2[d];
            float lr = lg > 0.f ? lg : 0.2f * lg;
            ev = __expf(-lr);
        }
        for (int j = 0; j < cnt; j++) {
            int   dj  = __shfl_sync(0xffffffffu, d, j);
            float evj = __shfl_sync(0xffffffffu, ev, j);
            rsum += evj;
            if (lane < 16) acc += evj * g_h2[dj * NC + lane];
        }
    }
    float v = acc / rsum;
    float e = v > 0.f ? v : (__expf(v) - 1.f);
    float m = e;
    #pragma unroll
    for (int o = 8; o; o >>= 1) m = fmaxf(m, __shfl_xor_sync(0xffffffffu, m, o, 16));
    float ex = __expf(e - m);
    float s = ex;
    #pragma unroll
    for (int o = 8; o; o >>= 1) s += __shfl_xor_sync(0xffffffffu, s, o, 16);
    if (lane < 16) out[(size_t)n * NC + lane] = (e - m) - __logf(s);
}

// ---------------- launch ----------------
extern "C" void kernel_launch(void* const* d_in, const int* in_sizes, int n_in,
                              void* d_out, int out_size) {
    const float* x  = (const float*)d_in[0];
    const int*   ei = (const int*)d_in[1];
    const float* W1 = (const float*)d_in[2];
    const float* a1 = (const float*)d_in[3];
    const float* W2 = (const float*)d_in[4];
    const float* a2 = (const float*)d_in[5];
    float* out = (float*)d_out;
    const int E = NE;
    const int* src = ei;
    const int* dst = ei + E;

    cudaFuncSetAttribute(gemm1_mma_kernel,
                         cudaFuncAttributeMaxDynamicSharedMemorySize, GEMM_SMEM);

    // CSR build (shared by both layers)
    zero_deg_kernel<<<(NN + 255) / 256, 256>>>();
    hist_kernel<<<(E + 255) / 256, 256>>>(src, E);
    scan_kernel<<<1, 1024>>>();
    init_cursor_kernel<<<(NN + 255) / 256, 256>>>();
    scatter_kernel<<<(E + 255) / 256, 256>>>(src, dst, E);

    // split-bf16 conversion
    convert_x_kernel<<<(int)(((size_t)NNPAD * NF / 4 + 255) / 256), 256>>>(x);
    convert_w_kernel<<<(HID1 * NF + 255) / 256, 256>>>(W1);

    // layer 1
    dim3 g1(NNPAD / 128, 4);
    gemm1_mma_kernel<<<g1, 256, GEMM_SMEM>>>();
    s1_kernel<<<(NN * 32 + 255) / 256, 256>>>(a1);
    agg1_kernel<<<NN, 128>>>();

    // layer 2 + output
    l2_kernel<<<(NN * 16 + 255) / 256, 256>>>(W2, a2);
    agg2_kernel<<<(NN * 32 + 255) / 256, 256>>>(out);
}

// round 4
// speedup vs baseline: 2.6192x; 1.2333x over previous
#include <cuda_runtime.h>
#include <cuda_bf16.h>
#include <cuda_fp16.h>
#include <cstdint>

#define NN    50000
#define NNPAD 50048
#define NF    512
#define NHID  64
#define H1N   8
#define NC    16
#define NE    1600000
#define HID1  512   /* H1N*NHID */

// ---------------- scratch (device globals; no allocations allowed) ----------
__device__ __half g_h1h [(size_t)NN * HID1];   // layer-1 features (fp16)
__device__ __half g_hp1h[(size_t)NN * HID1];   // layer-1 output = layer-2 input (fp16)
__device__ float g_ssrc1[NN * H1N];            // node-major [n][h]
__device__ float g_sdst1[NN * H1N];
__device__ float g_h2 [NN * NC];
__device__ float g_ss2[NN];
__device__ float g_sd2[NN];
__device__ int   g_deg[NN];
__device__ int   g_rowptr[NN + 1];
__device__ int   g_cursor[NN];
__device__ int   g_col[NE];
// bf16 split operands for tensor-core GEMM1
__device__ __nv_bfloat16 g_Xhi[(size_t)NNPAD * NF];
__device__ __nv_bfloat16 g_Xlo[(size_t)NNPAD * NF];
__device__ __nv_bfloat16 g_Bhi[HID1 * NF];   // [n][k] row-major (n = out feature)
__device__ __nv_bfloat16 g_Blo[HID1 * NF];

// ---------------- helpers ----------------
__device__ __forceinline__ uint32_t smem_u32(const void* p) {
    uint32_t a;
    asm("{ .reg .u64 t; cvta.to.shared.u64 t, %1; cvt.u32.u64 %0, t; }" : "=r"(a) : "l"(p));
    return a;
}
__device__ __forceinline__ void cp_async16(uint32_t dst, const void* src) {
    asm volatile("cp.async.cg.shared.global [%0], [%1], 16;" :: "r"(dst), "l"(src) : "memory");
}
__device__ __forceinline__ void cp_commit() {
    asm volatile("cp.async.commit_group;" ::: "memory");
}
template<int N>
__device__ __forceinline__ void cp_wait() {
    asm volatile("cp.async.wait_group %0;" :: "n"(N) : "memory");
}
__device__ __forceinline__ void ldsm4(uint32_t& r0, uint32_t& r1, uint32_t& r2, uint32_t& r3,
                                      uint32_t addr) {
    asm volatile("ldmatrix.sync.aligned.m8n8.x4.shared.b16 {%0,%1,%2,%3}, [%4];"
                 : "=r"(r0), "=r"(r1), "=r"(r2), "=r"(r3) : "r"(addr));
}
__device__ __forceinline__ void mma16816(float& c0, float& c1, float& c2, float& c3,
                                         uint32_t a0, uint32_t a1, uint32_t a2, uint32_t a3,
                                         uint32_t b0, uint32_t b1) {
    asm volatile("mma.sync.aligned.m16n8k16.row.col.f32.bf16.bf16.f32 "
                 "{%0,%1,%2,%3}, {%4,%5,%6,%7}, {%8,%9}, {%0,%1,%2,%3};"
                 : "+f"(c0), "+f"(c1), "+f"(c2), "+f"(c3)
                 : "r"(a0), "r"(a1), "r"(a2), "r"(a3), "r"(b0), "r"(b1));
}

// ---------------- CSR construction ----------------
__global__ void zero_deg_kernel() {
    int i = blockIdx.x * blockDim.x + threadIdx.x;
    if (i < NN) g_deg[i] = 0;
}
__global__ void hist_kernel(const int* __restrict__ src, int E) {
    int i = blockIdx.x * blockDim.x + threadIdx.x;
    if (i < E) atomicAdd(&g_deg[src[i]], 1);
}
__global__ void scan_kernel() {
    __shared__ int warpsums[32];
    __shared__ int s_carry;
    int t = threadIdx.x;
    int lane = t & 31, wid = t >> 5;
    if (t == 0) { s_carry = 0; g_rowptr[0] = 0; }
    __syncthreads();
    for (int base = 0; base < NN; base += 1024) {
        int idx = base + t;
        int v = (idx < NN) ? g_deg[idx] : 0;
        int x = v;
        #pragma unroll
        for (int o = 1; o < 32; o <<= 1) {
            int y = __shfl_up_sync(0xffffffffu, x, o);
            if (lane >= o) x += y;
        }
        if (lane == 31) warpsums[wid] = x;
        __syncthreads();
        if (wid == 0) {
            int w = warpsums[lane];
            #pragma unroll
            for (int o = 1; o < 32; o <<= 1) {
                int y = __shfl_up_sync(0xffffffffu, w, o);
                if (lane >= o) w += y;
            }
            warpsums[lane] = w;
        }
        __syncthreads();
        int warpoff = (wid > 0) ? warpsums[wid - 1] : 0;
        int incl = s_carry + warpoff + x;
        if (idx < NN) g_rowptr[idx + 1] = incl;
        __syncthreads();
        if (t == 1023) s_carry = incl;
        __syncthreads();
    }
}
__global__ void init_cursor_kernel() {
    int i = blockIdx.x * blockDim.x + threadIdx.x;
    if (i < NN) g_cursor[i] = g_rowptr[i];
}
__global__ void scatter_kernel(const int* __restrict__ src,
                               const int* __restrict__ dst, int E) {
    int i = blockIdx.x * blockDim.x + threadIdx.x;
    if (i < E) {
        int p = atomicAdd(&g_cursor[src[i]], 1);
        g_col[p] = dst[i];
    }
}

// ---------------- fp32 -> split bf16 converters ----------------
__device__ __forceinline__ void split_bf16(float v, __nv_bfloat16& hi, __nv_bfloat16& lo) {
    hi = __float2bfloat16_rn(v);
    lo = __float2bfloat16_rn(v - __bfloat162float(hi));
}
__global__ void convert_x_kernel(const float* __restrict__ X) {
    size_t i = (size_t)blockIdx.x * blockDim.x + threadIdx.x;   // per float4
    if (i >= (size_t)NNPAD * NF / 4) return;
    size_t base = i * 4;
    int row = (int)(base >> 9);
    float4 v = make_float4(0.f, 0.f, 0.f, 0.f);
    if (row < NN) v = *(const float4*)(X + base);
    __nv_bfloat16 h[4], l[4];
    split_bf16(v.x, h[0], l[0]); split_bf16(v.y, h[1], l[1]);
    split_bf16(v.z, h[2], l[2]); split_bf16(v.w, h[3], l[3]);
    uint2 ph, pl;
    ph.x = ((uint32_t)__bfloat16_as_ushort(h[1]) << 16) | __bfloat16_as_ushort(h[0]);
    ph.y = ((uint32_t)__bfloat16_as_ushort(h[3]) << 16) | __bfloat16_as_ushort(h[2]);
    pl.x = ((uint32_t)__bfloat16_as_ushort(l[1]) << 16) | __bfloat16_as_ushort(l[0]);
    pl.y = ((uint32_t)__bfloat16_as_ushort(l[3]) << 16) | __bfloat16_as_ushort(l[2]);
    *(uint2*)(g_Xhi + base) = ph;
    *(uint2*)(g_Xlo + base) = pl;
}
__global__ void convert_w_kernel(const float* __restrict__ W) {
    int tid = blockIdx.x * blockDim.x + threadIdx.x;   // tid = k*512 + n
    if (tid >= HID1 * NF) return;
    int k = tid >> 9, n = tid & 511;
    float w = W[(n >> 6) * (NF * NHID) + k * NHID + (n & 63)];
    __nv_bfloat16 hi, lo;
    split_bf16(w, hi, lo);
    g_Bhi[n * NF + k] = hi;
    g_Blo[n * NF + k] = lo;
}

// ---------------- GEMM1 via mma.sync (HMMA bf16, split) ----------------
// h1[NNPAD,512] = Xsplit @ Bsplit^T.  CTA tile 128x128x32, 8 warps (2x4), warp 64x32.
#define BK 32
#define TSTRIDE 40                         /* bf16 elems per smem row (32 + 8 pad) */
#define TILE_B (128 * TSTRIDE * 2)         /* 10240 bytes per matrix tile */
#define STAGE_B (4 * TILE_B)               /* Ahi,Alo,Bhi,Blo */
#define GEMM_SMEM (2 * STAGE_B)            /* 81920 */

__global__ __launch_bounds__(256, 2) void gemm1_mma_kernel() {
    extern __shared__ char smem[];
    const uint32_t sb = smem_u32(smem);
    const int tid = threadIdx.x;
    const int wid = tid >> 5, lane = tid & 31;
    const int wm = wid >> 2, wn = wid & 3;
    const int bm = blockIdx.x * 128;
    const int bn = blockIdx.y * 128;

    const int ldRow0 = tid >> 2;            // 0..63
    const int ldCol  = (tid & 3) * 8;       // bf16 col

    auto load_stage = [&](int s, int buf) {
        const int k0 = s * BK;
        const uint32_t st = sb + buf * STAGE_B;
        #pragma unroll
        for (int i = 0; i < 2; i++) {
            int row = ldRow0 + i * 64;
            uint32_t soff = (row * TSTRIDE + ldCol) * 2;
            cp_async16(st + 0 * TILE_B + soff, g_Xhi + (size_t)(bm + row) * NF + k0 + ldCol);
            cp_async16(st + 1 * TILE_B + soff, g_Xlo + (size_t)(bm + row) * NF + k0 + ldCol);
            cp_async16(st + 2 * TILE_B + soff, g_Bhi + (size_t)(bn + row) * NF + k0 + ldCol);
            cp_async16(st + 3 * TILE_B + soff, g_Blo + (size_t)(bn + row) * NF + k0 + ldCol);
        }
        cp_commit();
    };

    float acc[4][4][4];
    #pragma unroll
    for (int i = 0; i < 4; i++)
        #pragma unroll
        for (int j = 0; j < 4; j++)
            #pragma unroll
            for (int q = 0; q < 4; q++) acc[i][j][q] = 0.f;

    const uint32_t aRow = lane & 15;
    const uint32_t aCol = (lane & 16) >> 1;
    const uint32_t bRow = (lane & 7) + ((lane & 16) >> 1);
    const uint32_t bCol = (lane & 8) ? 8u : 0u;

    load_stage(0, 0);

    const int NSTAGE = NF / BK;   // 16
    for (int s = 0; s < NSTAGE; s++) {
        const int buf = s & 1;
        if (s + 1 < NSTAGE) {
            load_stage(s + 1, buf ^ 1);
            cp_wait<1>();
        } else {
            cp_wait<0>();
        }
        __syncthreads();

        const uint32_t st = sb + buf * STAGE_B;
        #pragma unroll
        for (int kk = 0; kk < 2; kk++) {
            const int k0 = kk * 16;
            uint32_t ah[4][4], al[4][4], bh[4][2], bl[4][2];
            #pragma unroll
            for (int mt = 0; mt < 4; mt++) {
                uint32_t off = ((wm * 64 + mt * 16 + aRow) * TSTRIDE + k0 + aCol) * 2;
                ldsm4(ah[mt][0], ah[mt][1], ah[mt][2], ah[mt][3], st + 0 * TILE_B + off);
                ldsm4(al[mt][0], al[mt][1], al[mt][2], al[mt][3], st + 1 * TILE_B + off);
            }
            #pragma unroll
            for (int np = 0; np < 2; np++) {
                uint32_t off = ((wn * 32 + np * 16 + bRow) * TSTRIDE + k0 + bCol) * 2;
                ldsm4(bh[np*2][0], bh[np*2][1], bh[np*2+1][0], bh[np*2+1][1],
                      st + 2 * TILE_B + off);
                ldsm4(bl[np*2][0], bl[np*2][1], bl[np*2+1][0], bl[np*2+1][1],
                      st + 3 * TILE_B + off);
            }
            #pragma unroll
            for (int mt = 0; mt < 4; mt++)
                #pragma unroll
                for (int nt = 0; nt < 4; nt++) {
                    mma16816(acc[mt][nt][0], acc[mt][nt][1], acc[mt][nt][2], acc[mt][nt][3],
                             ah[mt][0], ah[mt][1], ah[mt][2], ah[mt][3], bh[nt][0], bh[nt][1]);
                    mma16816(acc[mt][nt][0], acc[mt][nt][1], acc[mt][nt][2], acc[mt][nt][3],
                             ah[mt][0], ah[mt][1], ah[mt][2], ah[mt][3], bl[nt][0], bl[nt][1]);
                    mma16816(acc[mt][nt][0], acc[mt][nt][1], acc[mt][nt][2], acc[mt][nt][3],
                             al[mt][0], al[mt][1], al[mt][2], al[mt][3], bh[nt][0], bh[nt][1]);
                }
        }
        __syncthreads();
    }

    // epilogue -> fp16 h1
    const int erow = (lane >> 2);
    const int ecol = (lane & 3) * 2;
    #pragma unroll
    for (int mt = 0; mt < 4; mt++) {
        int r0 = bm + wm * 64 + mt * 16 + erow;
        #pragma unroll
        for (int nt = 0; nt < 4; nt++) {
            int c = bn + wn * 32 + nt * 8 + ecol;
            if (r0 < NN) {
                __half2 p = __floats2half2_rn(acc[mt][nt][0], acc[mt][nt][1]);
                *(__half2*)(g_h1h + (size_t)r0 * HID1 + c) = p;
            }
            if (r0 + 8 < NN) {
                __half2 p = __floats2half2_rn(acc[mt][nt][2], acc[mt][nt][3]);
                *(__half2*)(g_h1h + (size_t)(r0 + 8) * HID1 + c) = p;
            }
        }
    }
}

// ---------------- per-node attention scores, layer 1 (node-major out) -------
__global__ void s1_kernel(const float* __restrict__ a1) {
    int gw = (blockIdx.x * blockDim.x + threadIdx.x) >> 5;
    int lane = threadIdx.x & 31;
    if (gw >= NN) return;
    const __half* hrow = g_h1h + (size_t)gw * HID1;
    #pragma unroll
    for (int h = 0; h < H1N; ++h) {
        float x0 = __half2float(hrow[h * 64 + lane]);
        float x1 = __half2float(hrow[h * 64 + 32 + lane]);
        float vs = x0 * a1[h * 128 + lane]      + x1 * a1[h * 128 + 32 + lane];
        float vd = x0 * a1[h * 128 + 64 + lane] + x1 * a1[h * 128 + 96 + lane];
        #pragma unroll
        for (int o = 16; o; o >>= 1) {
            vs += __shfl_xor_sync(0xffffffffu, vs, o);
            vd += __shfl_xor_sync(0xffffffffu, vd, o);
        }
        if (lane == 0) { g_ssrc1[gw * H1N + h] = vs; g_sdst1[gw * H1N + h] = vd; }
    }
}

// ---------------- layer-1 edge aggregation (CSR, staged ev, fp16 gather) ----
__global__ __launch_bounds__(128) void agg1_kernel() {
    int n = blockIdx.x;
    int t = threadIdx.x;
    int head = t >> 4;          // aggregation head (feature group)
    int evh = t & 7;            // head this thread computes ev for
    __shared__ int   sc[128];
    __shared__ float sev[128 * H1N];
    int beg = g_rowptr[n], end = g_rowptr[n + 1];
    float ssh = g_ssrc1[n * H1N + evh];
    float4 acc = make_float4(0.f, 0.f, 0.f, 0.f);
    float rsum = 0.f;
    int c0 = t * 4;
    for (int base = beg; base < end; base += 128) {
        int cnt = min(128, end - base);
        if (t < cnt) sc[t] = g_col[base + t];
        __syncthreads();
        // stage ev[j][h]: thread t covers (j = t>>3 + 16*i, h = t&7)
        for (int j0 = (t >> 3); j0 < cnt; j0 += 16) {
            int d = sc[j0];
            float lg = ssh + __ldg(&g_sdst1[d * H1N + evh]);
            float lr = lg > 0.f ? lg : 0.2f * lg;
            sev[j0 * H1N + evh] = __expf(-lr);
        }
        __syncthreads();
        for (int j = 0; j < cnt; j++) {
            int d = sc[j];
            float ev = sev[j * H1N + head];
            rsum += ev;
            uint2 raw = *(const uint2*)(g_h1h + (size_t)d * HID1 + c0);
            float2 f01 = __half22float2(*(__half2*)&raw.x);
            float2 f23 = __half22float2(*(__half2*)&raw.y);
            acc.x += ev * f01.x; acc.y += ev * f01.y;
            acc.z += ev * f23.x; acc.w += ev * f23.y;
        }
        __syncthreads();
    }
    float inv = 1.f / rsum;
    float4 hp = make_float4(acc.x * inv, acc.y * inv, acc.z * inv, acc.w * inv);
    hp.x = hp.x > 0.f ? hp.x : (__expf(hp.x) - 1.f);
    hp.y = hp.y > 0.f ? hp.y : (__expf(hp.y) - 1.f);
    hp.z = hp.z > 0.f ? hp.z : (__expf(hp.z) - 1.f);
    hp.w = hp.w > 0.f ? hp.w : (__expf(hp.w) - 1.f);
    __half2 pa = __floats2half2_rn(hp.x, hp.y);
    __half2 pb = __floats2half2_rn(hp.z, hp.w);
    uint2 pk = make_uint2(*(uint32_t*)&pa, *(uint32_t*)&pb);
    *(uint2*)(g_hp1h + (size_t)n * HID1 + c0) = pk;
}

// ---------------- layer-2 GEMM (N=16) + scores ----------------
__global__ void l2_kernel(const float* __restrict__ W2, const float* __restrict__ a2) {
    int tid = blockIdx.x * blockDim.x + threadIdx.x;
    int n = tid >> 4, c = tid & 15;
    if (n >= NN) return;
    const __half* hrow = g_hp1h + (size_t)n * HID1;
    float acc = 0.f;
    for (int k = 0; k < HID1; k += 4) {
        uint2 raw = *(const uint2*)(hrow + k);
        float2 f01 = __half22float2(*(__half2*)&raw.x);
        float2 f23 = __half22float2(*(__half2*)&raw.y);
        acc += f01.x * W2[(k + 0) * NC + c];
        acc += f01.y * W2[(k + 1) * NC + c];
        acc += f23.x * W2[(k + 2) * NC + c];
        acc += f23.y * W2[(k + 3) * NC + c];
    }
    g_h2[n * NC + c] = acc;
    float ps = acc * a2[c], pd = acc * a2[NC + c];
    #pragma unroll
    for (int o = 8; o; o >>= 1) {
        ps += __shfl_xor_sync(0xffffffffu, ps, o, 16);
        pd += __shfl_xor_sync(0xffffffffu, pd, o, 16);
    }
    if (c == 0) { g_ss2[n] = ps; g_sd2[n] = pd; }
}

// ---------------- layer-2 aggregation + elu + log_softmax ----------------
__global__ void agg2_kernel(float* __restrict__ out) {
    int gw = (blockIdx.x * blockDim.x + threadIdx.x) >> 5;
    int lane = threadIdx.x & 31;
    if (gw >= NN) return;
    int n = gw;
    int beg = g_rowptr[n], end = g_rowptr[n + 1];
    float ss = g_ss2[n];
    float acc = 0.f, rsum = 0.f;
    for (int base = beg; base < end; base += 32) {
        int cnt = min(32, end - base);
        int d = 0; float ev = 0.f;
        if (lane < cnt) {
            d = g_col[base + lane];
            float lg = ss + g_sd2[d];
            float lr = lg > 0.f ? lg : 0.2f * lg;
            ev = __expf(-lr);
        }
        for (int j = 0; j < cnt; j++) {
            int   dj  = __shfl_sync(0xffffffffu, d, j);
            float evj = __shfl_sync(0xffffffffu, ev, j);
            rsum += evj;
            if (lane < 16) acc += evj * g_h2[dj * NC + lane];
        }
    }
    float v = acc / rsum;
    float e = v > 0.f ? v : (__expf(v) - 1.f);
    float m = e;
    #pragma unroll
    for (int o = 8; o; o >>= 1) m = fmaxf(m, __shfl_xor_sync(0xffffffffu, m, o, 16));
    float ex = __expf(e - m);
    float s = ex;
    #pragma unroll
    for (int o = 8; o; o >>= 1) s += __shfl_xor_sync(0xffffffffu, s, o, 16);
    if (lane < 16) out[(size_t)n * NC + lane] = (e - m) - __logf(s);
}

// ---------------- launch ----------------
extern "C" void kernel_launch(void* const* d_in, const int* in_sizes, int n_in,
                              void* d_out, int out_size) {
    const float* x  = (const float*)d_in[0];
    const int*   ei = (const int*)d_in[1];
    const float* W1 = (const float*)d_in[2];
    const float* a1 = (const float*)d_in[3];
    const float* W2 = (const float*)d_in[4];
    const float* a2 = (const float*)d_in[5];
    float* out = (float*)d_out;
    const int E = NE;
    const int* src = ei;
    const int* dst = ei + E;

    cudaFuncSetAttribute(gemm1_mma_kernel,
                         cudaFuncAttributeMaxDynamicSharedMemorySize, GEMM_SMEM);

    // CSR build (shared by both layers)
    zero_deg_kernel<<<(NN + 255) / 256, 256>>>();
    hist_kernel<<<(E + 255) / 256, 256>>>(src, E);
    scan_kernel<<<1, 1024>>>();
    init_cursor_kernel<<<(NN + 255) / 256, 256>>>();
    scatter_kernel<<<(E + 255) / 256, 256>>>(src, dst, E);

    // split-bf16 conversion
    convert_x_kernel<<<(int)(((size_t)NNPAD * NF / 4 + 255) / 256), 256>>>(x);
    convert_w_kernel<<<(HID1 * NF + 255) / 256, 256>>>(W1);

    // layer 1
    dim3 g1(NNPAD / 128, 4);
    gemm1_mma_kernel<<<g1, 256, GEMM_SMEM>>>();
    s1_kernel<<<(NN * 32 + 255) / 256, 256>>>(a1);
    agg1_kernel<<<NN, 128>>>();

    // layer 2 + output
    l2_kernel<<<(NN * 16 + 255) / 256, 256>>>(W2, a2);
    agg2_kernel<<<(NN * 32 + 255) / 256, 256>>>(out);
}

// round 5
// speedup vs baseline: 2.9668x; 1.1327x over previous
#include <cuda_runtime.h>
#include <cuda_bf16.h>
#include <cuda_fp16.h>
#include <cstdint>

#define NN    50000
#define NNPAD 50048
#define NF    512
#define NHID  64
#define H1N   8
#define NC    16
#define NE    1600000
#define HID1  512   /* H1N*NHID */

// ---------------- scratch (device globals; no allocations allowed) ----------
__device__ __half g_h1h [(size_t)NN * HID1];   // layer-1 features (fp16)
__device__ __half g_hp1h[(size_t)NN * HID1];   // layer-1 output = layer-2 input (fp16)
__device__ float g_ssrc1[NN * H1N];            // node-major [n][h]
__device__ float g_sdst1[NN * H1N];
__device__ float g_h2 [NN * NC];
__device__ float g_ss2[NN];
__device__ float g_sd2[NN];
__device__ int   g_deg[NN];
__device__ int   g_rowptr[NN + 1];
__device__ int   g_cursor[NN];
__device__ int   g_col[NE];
// bf16 operands for tensor-core GEMM1 (A single, B split)
__device__ __nv_bfloat16 g_Xhi[(size_t)NNPAD * NF];
__device__ __nv_bfloat16 g_Bhi[HID1 * NF];   // [n][k] row-major (n = out feature)
__device__ __nv_bfloat16 g_Blo[HID1 * NF];

// ---------------- helpers ----------------
__device__ __forceinline__ uint32_t smem_u32(const void* p) {
    uint32_t a;
    asm("{ .reg .u64 t; cvta.to.shared.u64 t, %1; cvt.u32.u64 %0, t; }" : "=r"(a) : "l"(p));
    return a;
}
__device__ __forceinline__ void cp_async16(uint32_t dst, const void* src) {
    asm volatile("cp.async.cg.shared.global [%0], [%1], 16;" :: "r"(dst), "l"(src) : "memory");
}
__device__ __forceinline__ void cp_commit() {
    asm volatile("cp.async.commit_group;" ::: "memory");
}
template<int N>
__device__ __forceinline__ void cp_wait() {
    asm volatile("cp.async.wait_group %0;" :: "n"(N) : "memory");
}
__device__ __forceinline__ void ldsm4(uint32_t& r0, uint32_t& r1, uint32_t& r2, uint32_t& r3,
                                      uint32_t addr) {
    asm volatile("ldmatrix.sync.aligned.m8n8.x4.shared.b16 {%0,%1,%2,%3}, [%4];"
                 : "=r"(r0), "=r"(r1), "=r"(r2), "=r"(r3) : "r"(addr));
}
__device__ __forceinline__ void mma16816(float& c0, float& c1, float& c2, float& c3,
                                         uint32_t a0, uint32_t a1, uint32_t a2, uint32_t a3,
                                         uint32_t b0, uint32_t b1) {
    asm volatile("mma.sync.aligned.m16n8k16.row.col.f32.bf16.bf16.f32 "
                 "{%0,%1,%2,%3}, {%4,%5,%6,%7}, {%8,%9}, {%0,%1,%2,%3};"
                 : "+f"(c0), "+f"(c1), "+f"(c2), "+f"(c3)
                 : "r"(a0), "r"(a1), "r"(a2), "r"(a3), "r"(b0), "r"(b1));
}

// ---------------- CSR construction ----------------
__global__ void zero_deg_kernel() {
    int i = blockIdx.x * blockDim.x + threadIdx.x;
    if (i < NN) g_deg[i] = 0;
}
__global__ void hist_kernel(const int* __restrict__ src, int E) {
    int i = blockIdx.x * blockDim.x + threadIdx.x;
    if (i < E) atomicAdd(&g_deg[src[i]], 1);
}
// single-block scan over 50000 ints; also writes exclusive prefix to g_cursor
__global__ void scan_kernel() {
    __shared__ int warpsums[32];
    __shared__ int s_carry;
    int t = threadIdx.x;
    int lane = t & 31, wid = t >> 5;
    if (t == 0) { s_carry = 0; g_rowptr[0] = 0; }
    __syncthreads();
    for (int base = 0; base < NN; base += 1024) {
        int idx = base + t;
        int v = (idx < NN) ? g_deg[idx] : 0;
        int x = v;
        #pragma unroll
        for (int o = 1; o < 32; o <<= 1) {
            int y = __shfl_up_sync(0xffffffffu, x, o);
            if (lane >= o) x += y;
        }
        if (lane == 31) warpsums[wid] = x;
        __syncthreads();
        if (wid == 0) {
            int w = warpsums[lane];
            #pragma unroll
            for (int o = 1; o < 32; o <<= 1) {
                int y = __shfl_up_sync(0xffffffffu, w, o);
                if (lane >= o) w += y;
            }
            warpsums[lane] = w;
        }
        __syncthreads();
        int warpoff = (wid > 0) ? warpsums[wid - 1] : 0;
        int incl = s_carry + warpoff + x;
        if (idx < NN) {
            g_rowptr[idx + 1] = incl;
            g_cursor[idx] = incl - v;     // exclusive prefix
        }
        __syncthreads();
        if (t == 1023) s_carry = incl;
        __syncthreads();
    }
}
__global__ void scatter_kernel(const int* __restrict__ src,
                               const int* __restrict__ dst, int E) {
    int i = blockIdx.x * blockDim.x + threadIdx.x;
    if (i < E) {
        int p = atomicAdd(&g_cursor[src[i]], 1);
        g_col[p] = dst[i];
    }
}

// ---------------- fp32 -> bf16 converters ----------------
__device__ __forceinline__ void split_bf16(float v, __nv_bfloat16& hi, __nv_bfloat16& lo) {
    hi = __float2bfloat16_rn(v);
    lo = __float2bfloat16_rn(v - __bfloat162float(hi));
}
__global__ void convert_x_kernel(const float* __restrict__ X) {
    size_t i = (size_t)blockIdx.x * blockDim.x + threadIdx.x;   // per float4
    if (i >= (size_t)NNPAD * NF / 4) return;
    size_t base = i * 4;
    int row = (int)(base >> 9);
    float4 v = make_float4(0.f, 0.f, 0.f, 0.f);
    if (row < NN) v = *(const float4*)(X + base);
    __nv_bfloat16 h0 = __float2bfloat16_rn(v.x), h1 = __float2bfloat16_rn(v.y);
    __nv_bfloat16 h2 = __float2bfloat16_rn(v.z), h3 = __float2bfloat16_rn(v.w);
    uint2 ph;
    ph.x = ((uint32_t)__bfloat16_as_ushort(h1) << 16) | __bfloat16_as_ushort(h0);
    ph.y = ((uint32_t)__bfloat16_as_ushort(h3) << 16) | __bfloat16_as_ushort(h2);
    *(uint2*)(g_Xhi + base) = ph;
}
__global__ void convert_w_kernel(const float* __restrict__ W) {
    int tid = blockIdx.x * blockDim.x + threadIdx.x;   // tid = k*512 + n
    if (tid >= HID1 * NF) return;
    int k = tid >> 9, n = tid & 511;
    float w = W[(n >> 6) * (NF * NHID) + k * NHID + (n & 63)];
    __nv_bfloat16 hi, lo;
    split_bf16(w, hi, lo);
    g_Bhi[n * NF + k] = hi;
    g_Blo[n * NF + k] = lo;
}

// ---------------- GEMM1 via mma.sync (HMMA bf16, B split) ----------------
// h1[NNPAD,512] = X @ Bsplit^T.  CTA tile 128x128x32, 8 warps (2x4), warp 64x32.
#define BK 32
#define TSTRIDE 40                         /* bf16 elems per smem row (32 + 8 pad) */
#define TILE_B (128 * TSTRIDE * 2)         /* 10240 bytes per matrix tile */
#define STAGE_B (3 * TILE_B)               /* A, Bhi, Blo */
#define GEMM_SMEM (2 * STAGE_B)            /* 61440 */

__global__ __launch_bounds__(256, 2) void gemm1_mma_kernel() {
    extern __shared__ char smem[];
    const uint32_t sb = smem_u32(smem);
    const int tid = threadIdx.x;
    const int wid = tid >> 5, lane = tid & 31;
    const int wm = wid >> 2, wn = wid & 3;
    const int bm = blockIdx.x * 128;
    const int bn = blockIdx.y * 128;

    const int ldRow0 = tid >> 2;            // 0..63
    const int ldCol  = (tid & 3) * 8;       // bf16 col

    auto load_stage = [&](int s, int buf) {
        const int k0 = s * BK;
        const uint32_t st = sb + buf * STAGE_B;
        #pragma unroll
        for (int i = 0; i < 2; i++) {
            int row = ldRow0 + i * 64;
            uint32_t soff = (row * TSTRIDE + ldCol) * 2;
            cp_async16(st + 0 * TILE_B + soff, g_Xhi + (size_t)(bm + row) * NF + k0 + ldCol);
            cp_async16(st + 1 * TILE_B + soff, g_Bhi + (size_t)(bn + row) * NF + k0 + ldCol);
            cp_async16(st + 2 * TILE_B + soff, g_Blo + (size_t)(bn + row) * NF + k0 + ldCol);
        }
        cp_commit();
    };

    float acc[4][4][4];
    #pragma unroll
    for (int i = 0; i < 4; i++)
        #pragma unroll
        for (int j = 0; j < 4; j++)
            #pragma unroll
            for (int q = 0; q < 4; q++) acc[i][j][q] = 0.f;

    const uint32_t aRow = lane & 15;
    const uint32_t aCol = (lane & 16) >> 1;
    const uint32_t bRow = (lane & 7) + ((lane & 16) >> 1);
    const uint32_t bCol = (lane & 8) ? 8u : 0u;

    load_stage(0, 0);

    const int NSTAGE = NF / BK;   // 16
    for (int s = 0; s < NSTAGE; s++) {
        const int buf = s & 1;
        if (s + 1 < NSTAGE) {
            load_stage(s + 1, buf ^ 1);
            cp_wait<1>();
        } else {
            cp_wait<0>();
        }
        __syncthreads();

        const uint32_t st = sb + buf * STAGE_B;
        #pragma unroll
        for (int kk = 0; kk < 2; kk++) {
            const int k0 = kk * 16;
            uint32_t ah[4][4], bh[4][2], bl[4][2];
            #pragma unroll
            for (int mt = 0; mt < 4; mt++) {
                uint32_t off = ((wm * 64 + mt * 16 + aRow) * TSTRIDE + k0 + aCol) * 2;
                ldsm4(ah[mt][0], ah[mt][1], ah[mt][2], ah[mt][3], st + 0 * TILE_B + off);
            }
            #pragma unroll
            for (int np = 0; np < 2; np++) {
                uint32_t off = ((wn * 32 + np * 16 + bRow) * TSTRIDE + k0 + bCol) * 2;
                ldsm4(bh[np*2][0], bh[np*2][1], bh[np*2+1][0], bh[np*2+1][1],
                      st + 1 * TILE_B + off);
                ldsm4(bl[np*2][0], bl[np*2][1], bl[np*2+1][0], bl[np*2+1][1],
                      st + 2 * TILE_B + off);
            }
            #pragma unroll
            for (int mt = 0; mt < 4; mt++)
                #pragma unroll
                for (int nt = 0; nt < 4; nt++) {
                    mma16816(acc[mt][nt][0], acc[mt][nt][1], acc[mt][nt][2], acc[mt][nt][3],
                             ah[mt][0], ah[mt][1], ah[mt][2], ah[mt][3], bh[nt][0], bh[nt][1]);
                    mma16816(acc[mt][nt][0], acc[mt][nt][1], acc[mt][nt][2], acc[mt][nt][3],
                             ah[mt][0], ah[mt][1], ah[mt][2], ah[mt][3], bl[nt][0], bl[nt][1]);
                }
        }
        __syncthreads();
    }

    // epilogue -> fp16 h1
    const int erow = (lane >> 2);
    const int ecol = (lane & 3) * 2;
    #pragma unroll
    for (int mt = 0; mt < 4; mt++) {
        int r0 = bm + wm * 64 + mt * 16 + erow;
        #pragma unroll
        for (int nt = 0; nt < 4; nt++) {
            int c = bn + wn * 32 + nt * 8 + ecol;
            if (r0 < NN) {
                __half2 p = __floats2half2_rn(acc[mt][nt][0], acc[mt][nt][1]);
                *(__half2*)(g_h1h + (size_t)r0 * HID1 + c) = p;
            }
            if (r0 + 8 < NN) {
                __half2 p = __floats2half2_rn(acc[mt][nt][2], acc[mt][nt][3]);
                *(__half2*)(g_h1h + (size_t)(r0 + 8) * HID1 + c) = p;
            }
        }
    }
}

// ---------------- per-node attention scores, layer 1 (node-major out) -------
__global__ void s1_kernel(const float* __restrict__ a1) {
    int gw = (blockIdx.x * blockDim.x + threadIdx.x) >> 5;
    int lane = threadIdx.x & 31;
    if (gw >= NN) return;
    const __half2* hrow = (const __half2*)(g_h1h + (size_t)gw * HID1);
    #pragma unroll
    for (int h = 0; h < H1N; ++h) {
        float2 f = __half22float2(hrow[h * 32 + lane]);   // cols 2*lane, 2*lane+1
        float2 as = *(const float2*)(a1 + h * 128 + 2 * lane);
        float2 ad = *(const float2*)(a1 + h * 128 + 64 + 2 * lane);
        float vs = f.x * as.x + f.y * as.y;
        float vd = f.x * ad.x + f.y * ad.y;
        #pragma unroll
        for (int o = 16; o; o >>= 1) {
            vs += __shfl_xor_sync(0xffffffffu, vs, o);
            vd += __shfl_xor_sync(0xffffffffu, vd, o);
        }
        if (lane == 0) { g_ssrc1[gw * H1N + h] = vs; g_sdst1[gw * H1N + h] = vd; }
    }
}

// ---------------- layer-1 edge aggregation (CSR, staged ev, fp16 gather) ----
__global__ __launch_bounds__(128) void agg1_kernel() {
    int n = blockIdx.x;
    int t = threadIdx.x;
    int head = t >> 4;          // aggregation head (feature group)
    int evh = t & 7;            // head this thread computes ev for
    __shared__ int   sc[128];
    __shared__ float sev[128 * H1N];
    int beg = g_rowptr[n], end = g_rowptr[n + 1];
    float ssh = g_ssrc1[n * H1N + evh];
    float4 acc = make_float4(0.f, 0.f, 0.f, 0.f);
    float rsum = 0.f;
    int c0 = t * 4;
    for (int base = beg; base < end; base += 128) {
        int cnt = min(128, end - base);
        if (t < cnt) sc[t] = g_col[base + t];
        __syncthreads();
        // stage ev[j][h]: thread t covers (j = t>>3 + 16*i, h = t&7)
        for (int j0 = (t >> 3); j0 < cnt; j0 += 16) {
            int d = sc[j0];
            float lg = ssh + __ldg(&g_sdst1[d * H1N + evh]);
            float lr = lg > 0.f ? lg : 0.2f * lg;
            sev[j0 * H1N + evh] = __expf(-lr);
        }
        __syncthreads();
        int j = 0;
        for (; j + 4 <= cnt; j += 4) {
            int d0 = sc[j], d1 = sc[j+1], d2 = sc[j+2], d3 = sc[j+3];
            float e0 = sev[(j+0) * H1N + head];
            float e1 = sev[(j+1) * H1N + head];
            float e2 = sev[(j+2) * H1N + head];
            float e3 = sev[(j+3) * H1N + head];
            uint2 r0 = *(const uint2*)(g_h1h + (size_t)d0 * HID1 + c0);
            uint2 r1 = *(const uint2*)(g_h1h + (size_t)d1 * HID1 + c0);
            uint2 r2 = *(const uint2*)(g_h1h + (size_t)d2 * HID1 + c0);
            uint2 r3 = *(const uint2*)(g_h1h + (size_t)d3 * HID1 + c0);
            rsum += e0 + e1 + e2 + e3;
            float2 a, b;
            a = __half22float2(*(__half2*)&r0.x); b = __half22float2(*(__half2*)&r0.y);
            acc.x += e0 * a.x; acc.y += e0 * a.y; acc.z += e0 * b.x; acc.w += e0 * b.y;
            a = __half22float2(*(__half2*)&r1.x); b = __half22float2(*(__half2*)&r1.y);
            acc.x += e1 * a.x; acc.y += e1 * a.y; acc.z += e1 * b.x; acc.w += e1 * b.y;
            a = __half22float2(*(__half2*)&r2.x); b = __half22float2(*(__half2*)&r2.y);
            acc.x += e2 * a.x; acc.y += e2 * a.y; acc.z += e2 * b.x; acc.w += e2 * b.y;
            a = __half22float2(*(__half2*)&r3.x); b = __half22float2(*(__half2*)&r3.y);
            acc.x += e3 * a.x; acc.y += e3 * a.y; acc.z += e3 * b.x; acc.w += e3 * b.y;
        }
        for (; j < cnt; j++) {
            int d = sc[j];
            float ev = sev[j * H1N + head];
            rsum += ev;
            uint2 raw = *(const uint2*)(g_h1h + (size_t)d * HID1 + c0);
            float2 f01 = __half22float2(*(__half2*)&raw.x);
            float2 f23 = __half22float2(*(__half2*)&raw.y);
            acc.x += ev * f01.x; acc.y += ev * f01.y;
            acc.z += ev * f23.x; acc.w += ev * f23.y;
        }
        __syncthreads();
    }
    float inv = 1.f / rsum;
    float4 hp = make_float4(acc.x * inv, acc.y * inv, acc.z * inv, acc.w * inv);
    hp.x = hp.x > 0.f ? hp.x : (__expf(hp.x) - 1.f);
    hp.y = hp.y > 0.f ? hp.y : (__expf(hp.y) - 1.f);
    hp.z = hp.z > 0.f ? hp.z : (__expf(hp.z) - 1.f);
    hp.w = hp.w > 0.f ? hp.w : (__expf(hp.w) - 1.f);
    __half2 pa = __floats2half2_rn(hp.x, hp.y);
    __half2 pb = __floats2half2_rn(hp.z, hp.w);
    uint2 pk = make_uint2(*(uint32_t*)&pa, *(uint32_t*)&pb);
    *(uint2*)(g_hp1h + (size_t)n * HID1 + c0) = pk;
}

// ---------------- layer-2 GEMM (N=16) + scores ----------------
__global__ void l2_kernel(const float* __restrict__ W2, const float* __restrict__ a2) {
    int tid = blockIdx.x * blockDim.x + threadIdx.x;
    int n = tid >> 4, c = tid & 15;
    if (n >= NN) return;
    const __half* hrow = g_hp1h + (size_t)n * HID1;
    float acc = 0.f;
    for (int k = 0; k < HID1; k += 4) {
        uint2 raw = *(const uint2*)(hrow + k);
        float2 f01 = __half22float2(*(__half2*)&raw.x);
        float2 f23 = __half22float2(*(__half2*)&raw.y);
        acc += f01.x * W2[(k + 0) * NC + c];
        acc += f01.y * W2[(k + 1) * NC + c];
        acc += f23.x * W2[(k + 2) * NC + c];
        acc += f23.y * W2[(k + 3) * NC + c];
    }
    g_h2[n * NC + c] = acc;
    float ps = acc * a2[c], pd = acc * a2[NC + c];
    #pragma unroll
    for (int o = 8; o; o >>= 1) {
        ps += __shfl_xor_sync(0xffffffffu, ps, o, 16);
        pd += __shfl_xor_sync(0xffffffffu, pd, o, 16);
    }
    if (c == 0) { g_ss2[n] = ps; g_sd2[n] = pd; }
}

// ---------------- layer-2 aggregation + elu + log_softmax ----------------
__global__ void agg2_kernel(float* __restrict__ out) {
    int gw = (blockIdx.x * blockDim.x + threadIdx.x) >> 5;
    int lane = threadIdx.x & 31;
    if (gw >= NN) return;
    int n = gw;
    int beg = g_rowptr[n], end = g_rowptr[n + 1];
    float ss = g_ss2[n];
    float acc = 0.f, rsum = 0.f;
    for (int base = beg; base < end; base += 32) {
        int cnt = min(32, end - base);
        int d = 0; float ev = 0.f;
        if (lane < cnt) {
            d = g_col[base + lane];
            float lg = ss + g_sd2[d];
            float lr = lg > 0.f ? lg : 0.2f * lg;
            ev = __expf(-lr);
        }
        for (int j = 0; j < cnt; j++) {
            int   dj  = __shfl_sync(0xffffffffu, d, j);
            float evj = __shfl_sync(0xffffffffu, ev, j);
            rsum += evj;
            if (lane < 16) acc += evj * g_h2[dj * NC + lane];
        }
    }
    float v = acc / rsum;
    float e = v > 0.f ? v : (__expf(v) - 1.f);
    float m = e;
    #pragma unroll
    for (int o = 8; o; o >>= 1) m = fmaxf(m, __shfl_xor_sync(0xffffffffu, m, o, 16));
    float ex = __expf(e - m);
    float s = ex;
    #pragma unroll
    for (int o = 8; o; o >>= 1) s += __shfl_xor_sync(0xffffffffu, s, o, 16);
    if (lane < 16) out[(size_t)n * NC + lane] = (e - m) - __logf(s);
}

// ---------------- launch ----------------
extern "C" void kernel_launch(void* const* d_in, const int* in_sizes, int n_in,
                              void* d_out, int out_size) {
    const float* x  = (const float*)d_in[0];
    const int*   ei = (const int*)d_in[1];
    const float* W1 = (const float*)d_in[2];
    const float* a1 = (const float*)d_in[3];
    const float* W2 = (const float*)d_in[4];
    const float* a2 = (const float*)d_in[5];
    float* out = (float*)d_out;
    const int E = NE;
    const int* src = ei;
    const int* dst = ei + E;

    cudaFuncSetAttribute(gemm1_mma_kernel,
                         cudaFuncAttributeMaxDynamicSharedMemorySize, GEMM_SMEM);

    // CSR build (shared by both layers)
    zero_deg_kernel<<<(NN + 255) / 256, 256>>>();
    hist_kernel<<<(E + 255) / 256, 256>>>(src, E);
    scan_kernel<<<1, 1024>>>();
    scatter_kernel<<<(E + 255) / 256, 256>>>(src, dst, E);

    // bf16 conversion
    convert_x_kernel<<<(int)(((size_t)NNPAD * NF / 4 + 255) / 256), 256>>>(x);
    convert_w_kernel<<<(HID1 * NF + 255) / 256, 256>>>(W1);

    // layer 1
    dim3 g1(NNPAD / 128, 4);
    gemm1_mma_kernel<<<g1, 256, GEMM_SMEM>>>();
    s1_kernel<<<(NN * 32 + 255) / 256, 256>>>(a1);
    agg1_kernel<<<NN, 128>>>();

    // layer 2 + output
    l2_kernel<<<(NN * 16 + 255) / 256, 256>>>(W2, a2);
    agg2_kernel<<<(NN * 32 + 255) / 256, 256>>>(out);
}

// round 7
// speedup vs baseline: 3.0872x; 1.0406x over previous
#include <cuda_runtime.h>
#include <cuda_bf16.h>
#include <cuda_fp16.h>
#include <cstdint>

#define NN    50000
#define NNPAD 50048
#define NF    512
#define NHID  64
#define H1N   8
#define NC    16
#define NE    1600000
#define HID1  512   /* H1N*NHID */

// ---------------- scratch (device globals; no allocations allowed) ----------
__device__ __half g_h1h [(size_t)NN * HID1];   // layer-1 features (fp16)
__device__ __half g_hp1h[(size_t)NN * HID1];   // layer-1 output = layer-2 input (fp16)
__device__ float g_ssrc1[NN * H1N];            // node-major [n][h]
__device__ float g_sdst1[NN * H1N];
__device__ float g_h2 [NN * NC];
__device__ float g_ss2[NN];
__device__ float g_sd2[NN];
__device__ int   g_deg[NN];
__device__ int   g_rowptr[NN + 1];
__device__ int   g_cursor[NN];
__device__ int   g_col[NE];
// bf16 operands for tensor-core GEMM1 (A single, B split)
__device__ __nv_bfloat16 g_Xhi[(size_t)NNPAD * NF];
__device__ __nv_bfloat16 g_Bhi[HID1 * NF];   // [n][k] row-major (n = out feature)
__device__ __nv_bfloat16 g_Blo[HID1 * NF];

// ---------------- helpers ----------------
__device__ __forceinline__ uint32_t smem_u32(const void* p) {
    uint32_t a;
    asm("{ .reg .u64 t; cvta.to.shared.u64 t, %1; cvt.u32.u64 %0, t; }" : "=r"(a) : "l"(p));
    return a;
}
__device__ __forceinline__ void cp_async16(uint32_t dst, const void* src) {
    asm volatile("cp.async.cg.shared.global [%0], [%1], 16;" :: "r"(dst), "l"(src) : "memory");
}
__device__ __forceinline__ void cp_commit() {
    asm volatile("cp.async.commit_group;" ::: "memory");
}
template<int N>
__device__ __forceinline__ void cp_wait() {
    asm volatile("cp.async.wait_group %0;" :: "n"(N) : "memory");
}
__device__ __forceinline__ void ldsm4(uint32_t& r0, uint32_t& r1, uint32_t& r2, uint32_t& r3,
                                      uint32_t addr) {
    asm volatile("ldmatrix.sync.aligned.m8n8.x4.shared.b16 {%0,%1,%2,%3}, [%4];"
                 : "=r"(r0), "=r"(r1), "=r"(r2), "=r"(r3) : "r"(addr));
}
__device__ __forceinline__ void mma16816(float& c0, float& c1, float& c2, float& c3,
                                         uint32_t a0, uint32_t a1, uint32_t a2, uint32_t a3,
                                         uint32_t b0, uint32_t b1) {
    asm volatile("mma.sync.aligned.m16n8k16.row.col.f32.bf16.bf16.f32 "
                 "{%0,%1,%2,%3}, {%4,%5,%6,%7}, {%8,%9}, {%0,%1,%2,%3};"
                 : "+f"(c0), "+f"(c1), "+f"(c2), "+f"(c3)
                 : "r"(a0), "r"(a1), "r"(a2), "r"(a3), "r"(b0), "r"(b1));
}

// ---------------- CSR construction + zeroing ----------------
__global__ void zero_kernel() {
    int i = blockIdx.x * blockDim.x + threadIdx.x;
    if (i < NN) g_deg[i] = 0;
    if (i < NN * H1N) { g_ssrc1[i] = 0.f; g_sdst1[i] = 0.f; }
}
__global__ void hist_kernel(const int* __restrict__ src, int E) {
    int i = blockIdx.x * blockDim.x + threadIdx.x;
    if (i < E) atomicAdd(&g_deg[src[i]], 1);
}
// single-block scan over 50000 ints; also writes exclusive prefix to g_cursor
__global__ void scan_kernel() {
    __shared__ int warpsums[32];
    __shared__ int s_carry;
    int t = threadIdx.x;
    int lane = t & 31, wid = t >> 5;
    if (t == 0) { s_carry = 0; g_rowptr[0] = 0; }
    __syncthreads();
    for (int base = 0; base < NN; base += 1024) {
        int idx = base + t;
        int v = (idx < NN) ? g_deg[idx] : 0;
        int x = v;
        #pragma unroll
        for (int o = 1; o < 32; o <<= 1) {
            int y = __shfl_up_sync(0xffffffffu, x, o);
            if (lane >= o) x += y;
        }
        if (lane == 31) warpsums[wid] = x;
        __syncthreads();
        if (wid == 0) {
            int w = warpsums[lane];
            #pragma unroll
            for (int o = 1; o < 32; o <<= 1) {
                int y = __shfl_up_sync(0xffffffffu, w, o);
                if (lane >= o) w += y;
            }
            warpsums[lane] = w;
        }
        __syncthreads();
        int warpoff = (wid > 0) ? warpsums[wid - 1] : 0;
        int incl = s_carry + warpoff + x;
        if (idx < NN) {
            g_rowptr[idx + 1] = incl;
            g_cursor[idx] = incl - v;     // exclusive prefix
        }
        __syncthreads();
        if (t == 1023) s_carry = incl;
        __syncthreads();
    }
}
__global__ void scatter_kernel(const int* __restrict__ src,
                               const int* __restrict__ dst, int E) {
    int i = blockIdx.x * blockDim.x + threadIdx.x;
    if (i < E) {
        int p = atomicAdd(&g_cursor[src[i]], 1);
        g_col[p] = dst[i];
    }
}

// ---------------- fp32 -> bf16 converters ----------------
__device__ __forceinline__ void split_bf16(float v, __nv_bfloat16& hi, __nv_bfloat16& lo) {
    hi = __float2bfloat16_rn(v);
    lo = __float2bfloat16_rn(v - __bfloat162float(hi));
}
__global__ void convert_x_kernel(const float* __restrict__ X) {
    size_t i = (size_t)blockIdx.x * blockDim.x + threadIdx.x;   // per float4
    if (i >= (size_t)NNPAD * NF / 4) return;
    size_t base = i * 4;
    int row = (int)(base >> 9);
    float4 v = make_float4(0.f, 0.f, 0.f, 0.f);
    if (row < NN) v = *(const float4*)(X + base);
    __nv_bfloat16 h0 = __float2bfloat16_rn(v.x), h1 = __float2bfloat16_rn(v.y);
    __nv_bfloat16 h2 = __float2bfloat16_rn(v.z), h3 = __float2bfloat16_rn(v.w);
    uint2 ph;
    ph.x = ((uint32_t)__bfloat16_as_ushort(h1) << 16) | __bfloat16_as_ushort(h0);
    ph.y = ((uint32_t)__bfloat16_as_ushort(h3) << 16) | __bfloat16_as_ushort(h2);
    *(uint2*)(g_Xhi + base) = ph;
}
__global__ void convert_w_kernel(const float* __restrict__ W) {
    int tid = blockIdx.x * blockDim.x + threadIdx.x;   // tid = k*512 + n
    if (tid >= HID1 * NF) return;
    int k = tid >> 9, n = tid & 511;
    float w = W[(n >> 6) * (NF * NHID) + k * NHID + (n & 63)];
    __nv_bfloat16 hi, lo;
    split_bf16(w, hi, lo);
    g_Bhi[n * NF + k] = hi;
    g_Blo[n * NF + k] = lo;
}

// ---------------- GEMM1 via mma.sync (HMMA bf16, B split) + fused scores ----
// h1[NNPAD,512] = X @ Bsplit^T.  CTA tile 128x128x32, 8 warps (2x4), warp 64x32.
#define BK 32
#define TSTRIDE 40                         /* bf16 elems per smem row (32 + 8 pad) */
#define TILE_B (128 * TSTRIDE * 2)         /* 10240 bytes per matrix tile */
#define STAGE_B (3 * TILE_B)               /* A, Bhi, Blo */
#define GEMM_SMEM (2 * STAGE_B)            /* 61440 */

__global__ __launch_bounds__(256, 2) void gemm1_mma_kernel(const float* __restrict__ a1) {
    extern __shared__ char smem[];
    const uint32_t sb = smem_u32(smem);
    const int tid = threadIdx.x;
    const int wid = tid >> 5, lane = tid & 31;
    const int wm = wid >> 2, wn = wid & 3;
    const int bm = blockIdx.x * 128;
    const int bn = blockIdx.y * 128;

    const int ldRow0 = tid >> 2;            // 0..63
    const int ldCol  = (tid & 3) * 8;       // bf16 col

    auto load_stage = [&](int s, int buf) {
        const int k0 = s * BK;
        const uint32_t st = sb + buf * STAGE_B;
        #pragma unroll
        for (int i = 0; i < 2; i++) {
            int row = ldRow0 + i * 64;
            uint32_t soff = (row * TSTRIDE + ldCol) * 2;
            cp_async16(st + 0 * TILE_B + soff, g_Xhi + (size_t)(bm + row) * NF + k0 + ldCol);
            cp_async16(st + 1 * TILE_B + soff, g_Bhi + (size_t)(bn + row) * NF + k0 + ldCol);
            cp_async16(st + 2 * TILE_B + soff, g_Blo + (size_t)(bn + row) * NF + k0 + ldCol);
        }
        cp_commit();
    };

    float acc[4][4][4];
    #pragma unroll
    for (int i = 0; i < 4; i++)
        #pragma unroll
        for (int j = 0; j < 4; j++)
            #pragma unroll
            for (int q = 0; q < 4; q++) acc[i][j][q] = 0.f;

    const uint32_t aRow = lane & 15;
    const uint32_t aCol = (lane & 16) >> 1;
    const uint32_t bRow = (lane & 7) + ((lane & 16) >> 1);
    const uint32_t bCol = (lane & 8) ? 8u : 0u;

    load_stage(0, 0);

    const int NSTAGE = NF / BK;   // 16
    for (int s = 0; s < NSTAGE; s++) {
        const int buf = s & 1;
        if (s + 1 < NSTAGE) {
            load_stage(s + 1, buf ^ 1);
            cp_wait<1>();
        } else {
            cp_wait<0>();
        }
        __syncthreads();

        const uint32_t st = sb + buf * STAGE_B;
        #pragma unroll
        for (int kk = 0; kk < 2; kk++) {
            const int k0 = kk * 16;
            uint32_t ah[4][4], bh[4][2], bl[4][2];
            #pragma unroll
            for (int mt = 0; mt < 4; mt++) {
                uint32_t off = ((wm * 64 + mt * 16 + aRow) * TSTRIDE + k0 + aCol) * 2;
                ldsm4(ah[mt][0], ah[mt][1], ah[mt][2], ah[mt][3], st + 0 * TILE_B + off);
            }
            #pragma unroll
            for (int np = 0; np < 2; np++) {
                uint32_t off = ((wn * 32 + np * 16 + bRow) * TSTRIDE + k0 + bCol) * 2;
                ldsm4(bh[np*2][0], bh[np*2][1], bh[np*2+1][0], bh[np*2+1][1],
                      st + 1 * TILE_B + off);
                ldsm4(bl[np*2][0], bl[np*2][1], bl[np*2+1][0], bl[np*2+1][1],
                      st + 2 * TILE_B + off);
            }
            #pragma unroll
            for (int mt = 0; mt < 4; mt++)
                #pragma unroll
                for (int nt = 0; nt < 4; nt++) {
                    mma16816(acc[mt][nt][0], acc[mt][nt][1], acc[mt][nt][2], acc[mt][nt][3],
                             ah[mt][0], ah[mt][1], ah[mt][2], ah[mt][3], bh[nt][0], bh[nt][1]);
                    mma16816(acc[mt][nt][0], acc[mt][nt][1], acc[mt][nt][2], acc[mt][nt][3],
                             ah[mt][0], ah[mt][1], ah[mt][2], ah[mt][3], bl[nt][0], bl[nt][1]);
                }
        }
        __syncthreads();
    }

    // ---- epilogue A: store fp16 h1 ----
    const int erow = (lane >> 2);
    const int ecol = (lane & 3) * 2;
    #pragma unroll
    for (int mt = 0; mt < 4; mt++) {
        int r0 = bm + wm * 64 + mt * 16 + erow;
        #pragma unroll
        for (int nt = 0; nt < 4; nt++) {
            int c = bn + wn * 32 + nt * 8 + ecol;
            if (r0 < NN) {
                __half2 p = __floats2half2_rn(acc[mt][nt][0], acc[mt][nt][1]);
                *(__half2*)(g_h1h + (size_t)r0 * HID1 + c) = p;
            }
            if (r0 + 8 < NN) {
                __half2 p = __floats2half2_rn(acc[mt][nt][2], acc[mt][nt][3]);
                *(__half2*)(g_h1h + (size_t)(r0 + 8) * HID1 + c) = p;
            }
        }
    }

    // ---- epilogue B: fused attention-score partial dots ----
    // all cols of this warp live in head h; feat f = (wn&1)*32 + nt*8 + ecol
    {
        const int h = (bn >> 6) + (wn >> 1);
        const int fbase = (wn & 1) * 32;
        float asv[4][2], adv[4][2];
        #pragma unroll
        for (int nt = 0; nt < 4; nt++) {
            int f = fbase + nt * 8 + ecol;
            asv[nt][0] = __ldg(&a1[h * 128 + f]);
            asv[nt][1] = __ldg(&a1[h * 128 + f + 1]);
            adv[nt][0] = __ldg(&a1[h * 128 + 64 + f]);
            adv[nt][1] = __ldg(&a1[h * 128 + 64 + f + 1]);
        }
        #pragma unroll
        for (int mt = 0; mt < 4; mt++) {
            float ps0 = 0.f, pd0 = 0.f, ps8 = 0.f, pd8 = 0.f;
            #pragma unroll
            for (int nt = 0; nt < 4; nt++) {
                ps0 += acc[mt][nt][0] * asv[nt][0] + acc[mt][nt][1] * asv[nt][1];
                pd0 += acc[mt][nt][0] * adv[nt][0] + acc[mt][nt][1] * adv[nt][1];
                ps8 += acc[mt][nt][2] * asv[nt][0] + acc[mt][nt][3] * asv[nt][1];
                pd8 += acc[mt][nt][2] * adv[nt][0] + acc[mt][nt][3] * adv[nt][1];
            }
            #pragma unroll
            for (int o = 1; o <= 2; o <<= 1) {
                ps0 += __shfl_xor_sync(0xffffffffu, ps0, o);
                pd0 += __shfl_xor_sync(0xffffffffu, pd0, o);
                ps8 += __shfl_xor_sync(0xffffffffu, ps8, o);
                pd8 += __shfl_xor_sync(0xffffffffu, pd8, o);
            }
            if ((lane & 3) == 0) {
                int r0 = bm + wm * 64 + mt * 16 + erow;
                if (r0 < NN) {
                    atomicAdd(&g_ssrc1[r0 * H1N + h], ps0);
                    atomicAdd(&g_sdst1[r0 * H1N + h], pd0);
                }
                if (r0 + 8 < NN) {
                    atomicAdd(&g_ssrc1[(r0 + 8) * H1N + h], ps8);
                    atomicAdd(&g_sdst1[(r0 + 8) * H1N + h], pd8);
                }
            }
        }
    }
}

// ---------------- layer-1 edge aggregation (CSR, staged ev, fp16 gather) ----
__global__ __launch_bounds__(128) void agg1_kernel() {
    int n = blockIdx.x;
    int t = threadIdx.x;
    int head = t >> 4;          // aggregation head (feature group)
    int evh = t & 7;            // head this thread computes ev for
    __shared__ int   sc[128];
    __shared__ float sev[128 * H1N];
    int beg = g_rowptr[n], end = g_rowptr[n + 1];
    float ssh = g_ssrc1[n * H1N + evh];
    float4 acc = make_float4(0.f, 0.f, 0.f, 0.f);
    float rsum = 0.f;
    int c0 = t * 4;
    for (int base = beg; base < end; base += 128) {
        int cnt = min(128, end - base);
        if (t < cnt) sc[t] = g_col[base + t];
        __syncthreads();
        for (int j0 = (t >> 3); j0 < cnt; j0 += 16) {
            int d = sc[j0];
            float lg = ssh + __ldg(&g_sdst1[d * H1N + evh]);
            float lr = lg > 0.f ? lg : 0.2f * lg;
            sev[j0 * H1N + evh] = __expf(-lr);
        }
        __syncthreads();
        int j = 0;
        for (; j + 4 <= cnt; j += 4) {
            int d0 = sc[j], d1 = sc[j+1], d2 = sc[j+2], d3 = sc[j+3];
            float e0 = sev[(j+0) * H1N + head];
            float e1 = sev[(j+1) * H1N + head];
            float e2 = sev[(j+2) * H1N + head];
            float e3 = sev[(j+3) * H1N + head];
            uint2 r0 = *(const uint2*)(g_h1h + (size_t)d0 * HID1 + c0);
            uint2 r1 = *(const uint2*)(g_h1h + (size_t)d1 * HID1 + c0);
            uint2 r2 = *(const uint2*)(g_h1h + (size_t)d2 * HID1 + c0);
            uint2 r3 = *(const uint2*)(g_h1h + (size_t)d3 * HID1 + c0);
            rsum += e0 + e1 + e2 + e3;
            float2 a, b;
            a = __half22float2(*(__half2*)&r0.x); b = __half22float2(*(__half2*)&r0.y);
            acc.x += e0 * a.x; acc.y += e0 * a.y; acc.z += e0 * b.x; acc.w += e0 * b.y;
            a = __half22float2(*(__half2*)&r1.x); b = __half22float2(*(__half2*)&r1.y);
            acc.x += e1 * a.x; acc.y += e1 * a.y; acc.z += e1 * b.x; acc.w += e1 * b.y;
            a = __half22float2(*(__half2*)&r2.x); b = __half22float2(*(__half2*)&r2.y);
            acc.x += e2 * a.x; acc.y += e2 * a.y; acc.z += e2 * b.x; acc.w += e2 * b.y;
            a = __half22float2(*(__half2*)&r3.x); b = __half22float2(*(__half2*)&r3.y);
            acc.x += e3 * a.x; acc.y += e3 * a.y; acc.z += e3 * b.x; acc.w += e3 * b.y;
        }
        for (; j < cnt; j++) {
            int d = sc[j];
            float ev = sev[j * H1N + head];
            rsum += ev;
            uint2 raw = *(const uint2*)(g_h1h + (size_t)d * HID1 + c0);
            float2 f01 = __half22float2(*(__half2*)&raw.x);
            float2 f23 = __half22float2(*(__half2*)&raw.y);
            acc.x += ev * f01.x; acc.y += ev * f01.y;
            acc.z += ev * f23.x; acc.w += ev * f23.y;
        }
        __syncthreads();
    }
    float inv = 1.f / rsum;
    float4 hp = make_float4(acc.x * inv, acc.y * inv, acc.z * inv, acc.w * inv);
    hp.x = hp.x > 0.f ? hp.x : (__expf(hp.x) - 1.f);
    hp.y = hp.y > 0.f ? hp.y : (__expf(hp.y) - 1.f);
    hp.z = hp.z > 0.f ? hp.z : (__expf(hp.z) - 1.f);
    hp.w = hp.w > 0.f ? hp.w : (__expf(hp.w) - 1.f);
    __half2 pa = __floats2half2_rn(hp.x, hp.y);
    __half2 pb = __floats2half2_rn(hp.z, hp.w);
    uint2 pk = make_uint2(*(uint32_t*)&pa, *(uint32_t*)&pb);
    *(uint2*)(g_hp1h + (size_t)n * HID1 + c0) = pk;
}

// ---------------- layer-2 GEMM (N=16) + scores ----------------
__global__ void l2_kernel(const float* __restrict__ W2, const float* __restrict__ a2) {
    int tid = blockIdx.x * blockDim.x + threadIdx.x;
    int n = tid >> 4, c = tid & 15;
    if (n >= NN) return;
    const __half* hrow = g_hp1h + (size_t)n * HID1;
    float acc = 0.f;
    for (int k = 0; k < HID1; k += 4) {
        uint2 raw = *(const uint2*)(hrow + k);
        float2 f01 = __half22float2(*(__half2*)&raw.x);
        float2 f23 = __half22float2(*(__half2*)&raw.y);
        acc += f01.x * W2[(k + 0) * NC + c];
        acc += f01.y * W2[(k + 1) * NC + c];
        acc += f23.x * W2[(k + 2) * NC + c];
        acc += f23.y * W2[(k + 3) * NC + c];
    }
    g_h2[n * NC + c] = acc;
    float ps = acc * a2[c], pd = acc * a2[NC + c];
    #pragma unroll
    for (int o = 8; o; o >>= 1) {
        ps += __shfl_xor_sync(0xffffffffu, ps, o, 16);
        pd += __shfl_xor_sync(0xffffffffu, pd, o, 16);
    }
    if (c == 0) { g_ss2[n] = ps; g_sd2[n] = pd; }
}

// ---------------- layer-2 aggregation + elu + log_softmax (edge-parallel) ---
__global__ void agg2_kernel(float* __restrict__ out) {
    int gw = (blockIdx.x * blockDim.x + threadIdx.x) >> 5;
    int lane = threadIdx.x & 31;
    if (gw >= NN) return;
    int n = gw;
    int beg = g_rowptr[n], end = g_rowptr[n + 1];
    float ss = g_ss2[n];
    float rsum = 0.f;
    float4 A0 = make_float4(0.f,0.f,0.f,0.f), A1 = A0, A2 = A0, A3 = A0;
    for (int e = beg + lane; e < end; e += 32) {
        int d = g_col[e];
        float lg = ss + __ldg(&g_sd2[d]);
        float lr = lg > 0.f ? lg : 0.2f * lg;
        float ev = __expf(-lr);
        rsum += ev;
        const float4* hp = (const float4*)(g_h2 + d * NC);
        float4 v0 = hp[0], v1 = hp[1], v2 = hp[2], v3 = hp[3];
        A0.x += ev*v0.x; A0.y += ev*v0.y; A0.z += ev*v0.z; A0.w += ev*v0.w;
        A1.x += ev*v1.x; A1.y += ev*v1.y; A1.z += ev*v1.z; A1.w += ev*v1.w;
        A2.x += ev*v2.x; A2.y += ev*v2.y; A2.z += ev*v2.z; A2.w += ev*v2.w;
        A3.x += ev*v3.x; A3.y += ev*v3.y; A3.z += ev*v3.z; A3.w += ev*v3.w;
    }
    #pragma unroll
    for (int o = 16; o; o >>= 1) {
        rsum += __shfl_xor_sync(0xffffffffu, rsum, o);
        A0.x += __shfl_xor_sync(0xffffffffu, A0.x, o);
        A0.y += __shfl_xor_sync(0xffffffffu, A0.y, o);
        A0.z += __shfl_xor_sync(0xffffffffu, A0.z, o);
        A0.w += __shfl_xor_sync(0xffffffffu, A0.w, o);
        A1.x += __shfl_xor_sync(0xffffffffu, A1.x, o);
        A1.y += __shfl_xor_sync(0xffffffffu, A1.y, o);
        A1.z += __shfl_xor_sync(0xffffffffu, A1.z, o);
        A1.w += __shfl_xor_sync(0xffffffffu, A1.w, o);
        A2.x += __shfl_xor_sync(0xffffffffu, A2.x, o);
        A2.y += __shfl_xor_sync(0xffffffffu, A2.y, o);
        A2.z += __shfl_xor_sync(0xffffffffu, A2.z, o);
        A2.w += __shfl_xor_sync(0xffffffffu, A2.w, o);
        A3.x += __shfl_xor_sync(0xffffffffu, A3.x, o);
        A3.y += __shfl_xor_sync(0xffffffffu, A3.y, o);
        A3.z += __shfl_xor_sync(0xffffffffu, A3.z, o);
        A3.w += __shfl_xor_sync(0xffffffffu, A3.w, o);
    }
    if (lane == 0) {
        float inv = 1.f / rsum;
        float e[16];
        e[0]=A0.x*inv; e[1]=A0.y*inv; e[2]=A0.z*inv; e[3]=A0.w*inv;
        e[4]=A1.x*inv; e[5]=A1.y*inv; e[6]=A1.z*inv; e[7]=A1.w*inv;
        e[8]=A2.x*inv; e[9]=A2.y*inv; e[10]=A2.z*inv; e[11]=A2.w*inv;
        e[12]=A3.x*inv; e[13]=A3.y*inv; e[14]=A3.z*inv; e[15]=A3.w*inv;
        float m = -1e30f;
        #pragma unroll
        for (int c = 0; c < 16; c++) {
            e[c] = e[c] > 0.f ? e[c] : (__expf(e[c]) - 1.f);   // elu
            m = fmaxf(m, e[c]);
        }
        float s = 0.f;
        #pragma unroll
        for (int c = 0; c < 16; c++) s += __expf(e[c] - m);
        float lse = m + __logf(s);
        float* o = out + (size_t)n * NC;
        *(float4*)(o + 0)  = make_float4(e[0]-lse, e[1]-lse, e[2]-lse, e[3]-lse);
        *(float4*)(o + 4)  = make_float4(e[4]-lse, e[5]-lse, e[6]-lse, e[7]-lse);
        *(float4*)(o + 8)  = make_float4(e[8]-lse, e[9]-lse, e[10]-lse, e[11]-lse);
        *(float4*)(o + 12) = make_float4(e[12]-lse, e[13]-lse, e[14]-lse, e[15]-lse);
    }
}

// ---------------- launch ----------------
extern "C" void kernel_launch(void* const* d_in, const int* in_sizes, int n_in,
                              void* d_out, int out_size) {
    const float* x  = (const float*)d_in[0];
    const int*   ei = (const int*)d_in[1];
    const float* W1 = (const float*)d_in[2];
    const float* a1 = (const float*)d_in[3];
    const float* W2 = (const float*)d_in[4];
    const float* a2 = (const float*)d_in[5];
    float* out = (float*)d_out;
    const int E = NE;
    const int* src = ei;
    const int* dst = ei + E;

    cudaFuncSetAttribute(gemm1_mma_kernel,
                         cudaFuncAttributeMaxDynamicSharedMemorySize, GEMM_SMEM);

    // zero deg + score accumulators; CSR build
    zero_kernel<<<(NN * H1N + 255) / 256, 256>>>();
    hist_kernel<<<(E + 255) / 256, 256>>>(src, E);
    scan_kernel<<<1, 1024>>>();
    scatter_kernel<<<(E + 255) / 256, 256>>>(src, dst, E);

    // bf16 conversion
    convert_x_kernel<<<(int)(((size_t)NNPAD * NF / 4 + 255) / 256), 256>>>(x);
    convert_w_kernel<<<(HID1 * NF + 255) / 256, 256>>>(W1);

    // layer 1 (GEMM + fused scores)
    dim3 g1(NNPAD / 128, 4);
    gemm1_mma_kernel<<<g1, 256, GEMM_SMEM>>>(a1);
    agg1_kernel<<<NN, 128>>>();

    // layer 2 + output
    l2_kernel<<<(NN * 16 + 255) / 256, 256>>>(W2, a2);
    agg2_kernel<<<(NN * 32 + 255) / 256, 256>>>(out);
}

// round 8
// speedup vs baseline: 3.5820x; 1.1603x over previous
#include <cuda_runtime.h>
#include <cuda_bf16.h>
#include <cuda_fp16.h>
#include <cstdint>

#define NN    50000
#define NNPAD 50048
#define NF    512
#define NHID  64
#define H1N   8
#define NC    16
#define NE    1600000
#define HID1  512   /* H1N*NHID */

// ---------------- scratch (device globals; no allocations allowed) ----------
__device__ __half g_h1h [(size_t)NN * HID1];   // layer-1 features (fp16)
__device__ __half g_hp1h[(size_t)NN * HID1];   // layer-1 output = layer-2 input (fp16)
__device__ float g_ssrc1[NN * H1N];            // node-major [n][h]
__device__ float g_sdst1[NN * H1N];
__device__ float g_h2 [NN * NC];
__device__ float g_ss2[NN];
__device__ float g_sd2[NN];
__device__ int   g_deg[NN];
__device__ int   g_rowptr[NN + 1];
__device__ int   g_cursor[NN];
__device__ int   g_col[NE];
// bf16 operands for tensor-core GEMM1
__device__ __nv_bfloat16 g_Xb[(size_t)NNPAD * NF];
__device__ __nv_bfloat16 g_Bb[HID1 * NF];   // [n][k] row-major (n = out feature)

// ---------------- helpers ----------------
__device__ __forceinline__ uint32_t smem_u32(const void* p) {
    uint32_t a;
    asm("{ .reg .u64 t; cvta.to.shared.u64 t, %1; cvt.u32.u64 %0, t; }" : "=r"(a) : "l"(p));
    return a;
}
__device__ __forceinline__ void cp_async16(uint32_t dst, const void* src) {
    asm volatile("cp.async.cg.shared.global [%0], [%1], 16;" :: "r"(dst), "l"(src) : "memory");
}
__device__ __forceinline__ void cp_commit() {
    asm volatile("cp.async.commit_group;" ::: "memory");
}
template<int N>
__device__ __forceinline__ void cp_wait() {
    asm volatile("cp.async.wait_group %0;" :: "n"(N) : "memory");
}
__device__ __forceinline__ void ldsm4(uint32_t& r0, uint32_t& r1, uint32_t& r2, uint32_t& r3,
                                      uint32_t addr) {
    asm volatile("ldmatrix.sync.aligned.m8n8.x4.shared.b16 {%0,%1,%2,%3}, [%4];"
                 : "=r"(r0), "=r"(r1), "=r"(r2), "=r"(r3) : "r"(addr));
}
__device__ __forceinline__ void mma16816(float& c0, float& c1, float& c2, float& c3,
                                         uint32_t a0, uint32_t a1, uint32_t a2, uint32_t a3,
                                         uint32_t b0, uint32_t b1) {
    asm volatile("mma.sync.aligned.m16n8k16.row.col.f32.bf16.bf16.f32 "
                 "{%0,%1,%2,%3}, {%4,%5,%6,%7}, {%8,%9}, {%0,%1,%2,%3};"
                 : "+f"(c0), "+f"(c1), "+f"(c2), "+f"(c3)
                 : "r"(a0), "r"(a1), "r"(a2), "r"(a3), "r"(b0), "r"(b1));
}

// ---------------- CSR construction + zeroing ----------------
__global__ void zero_kernel() {
    int i = blockIdx.x * blockDim.x + threadIdx.x;
    if (i < NN) g_deg[i] = 0;
    if (i < NN * H1N) { g_ssrc1[i] = 0.f; g_sdst1[i] = 0.f; }
}
__global__ void hist_kernel(const int* __restrict__ src, int E) {
    int i = blockIdx.x * blockDim.x + threadIdx.x;
    if (i < E) atomicAdd(&g_deg[src[i]], 1);
}
// single-block scan over 50000 ints; also writes exclusive prefix to g_cursor
__global__ void scan_kernel() {
    __shared__ int warpsums[32];
    __shared__ int s_carry;
    int t = threadIdx.x;
    int lane = t & 31, wid = t >> 5;
    if (t == 0) { s_carry = 0; g_rowptr[0] = 0; }
    __syncthreads();
    for (int base = 0; base < NN; base += 1024) {
        int idx = base + t;
        int v = (idx < NN) ? g_deg[idx] : 0;
        int x = v;
        #pragma unroll
        for (int o = 1; o < 32; o <<= 1) {
            int y = __shfl_up_sync(0xffffffffu, x, o);
            if (lane >= o) x += y;
        }
        if (lane == 31) warpsums[wid] = x;
        __syncthreads();
        if (wid == 0) {
            int w = warpsums[lane];
            #pragma unroll
            for (int o = 1; o < 32; o <<= 1) {
                int y = __shfl_up_sync(0xffffffffu, w, o);
                if (lane >= o) w += y;
            }
            warpsums[lane] = w;
        }
        __syncthreads();
        int warpoff = (wid > 0) ? warpsums[wid - 1] : 0;
        int incl = s_carry + warpoff + x;
        if (idx < NN) {
            g_rowptr[idx + 1] = incl;
            g_cursor[idx] = incl - v;     // exclusive prefix
        }
        __syncthreads();
        if (t == 1023) s_carry = incl;
        __syncthreads();
    }
}
__global__ void scatter_kernel(const int* __restrict__ src,
                               const int* __restrict__ dst, int E) {
    int i = blockIdx.x * blockDim.x + threadIdx.x;
    if (i < E) {
        int p = atomicAdd(&g_cursor[src[i]], 1);
        g_col[p] = dst[i];
    }
}

// ---------------- fp32 -> bf16 converters ----------------
__global__ void convert_x_kernel(const float* __restrict__ X) {
    size_t i = (size_t)blockIdx.x * blockDim.x + threadIdx.x;   // per float4
    if (i >= (size_t)NNPAD * NF / 4) return;
    size_t base = i * 4;
    int row = (int)(base >> 9);
    float4 v = make_float4(0.f, 0.f, 0.f, 0.f);
    if (row < NN) v = *(const float4*)(X + base);
    __nv_bfloat16 h0 = __float2bfloat16_rn(v.x), h1 = __float2bfloat16_rn(v.y);
    __nv_bfloat16 h2 = __float2bfloat16_rn(v.z), h3 = __float2bfloat16_rn(v.w);
    uint2 ph;
    ph.x = ((uint32_t)__bfloat16_as_ushort(h1) << 16) | __bfloat16_as_ushort(h0);
    ph.y = ((uint32_t)__bfloat16_as_ushort(h3) << 16) | __bfloat16_as_ushort(h2);
    *(uint2*)(g_Xb + base) = ph;
}
__global__ void convert_w_kernel(const float* __restrict__ W) {
    int tid = blockIdx.x * blockDim.x + threadIdx.x;   // tid = k*512 + n
    if (tid >= HID1 * NF) return;
    int k = tid >> 9, n = tid & 511;
    float w = W[(n >> 6) * (NF * NHID) + k * NHID + (n & 63)];
    g_Bb[n * NF + k] = __float2bfloat16_rn(w);
}

// ---------------- GEMM1 via mma.sync (HMMA bf16) + fused scores ----
// h1[NNPAD,512] = X @ B^T.  CTA tile 128x128x32, 8 warps (2x4), warp 64x32.
// 3-stage cp.async pipeline.
#define BK 32
#define TSTRIDE 40                         /* bf16 elems per smem row (32 + 8 pad) */
#define TILE_B (128 * TSTRIDE * 2)         /* 10240 bytes per matrix tile */
#define STAGE_B (2 * TILE_B)               /* A, B */
#define GEMM_SMEM (3 * STAGE_B)            /* 61440 */

__global__ __launch_bounds__(256, 2) void gemm1_mma_kernel(const float* __restrict__ a1) {
    extern __shared__ char smem[];
    const uint32_t sb = smem_u32(smem);
    const int tid = threadIdx.x;
    const int wid = tid >> 5, lane = tid & 31;
    const int wm = wid >> 2, wn = wid & 3;
    const int bm = blockIdx.x * 128;
    const int bn = blockIdx.y * 128;

    const int ldRow0 = tid >> 2;            // 0..63
    const int ldCol  = (tid & 3) * 8;       // bf16 col

    auto load_stage = [&](int s, int buf) {
        const int k0 = s * BK;
        const uint32_t st = sb + buf * STAGE_B;
        #pragma unroll
        for (int i = 0; i < 2; i++) {
            int row = ldRow0 + i * 64;
            uint32_t soff = (row * TSTRIDE + ldCol) * 2;
            cp_async16(st + 0 * TILE_B + soff, g_Xb + (size_t)(bm + row) * NF + k0 + ldCol);
            cp_async16(st + 1 * TILE_B + soff, g_Bb + (size_t)(bn + row) * NF + k0 + ldCol);
        }
        cp_commit();
    };

    float acc[4][4][4];
    #pragma unroll
    for (int i = 0; i < 4; i++)
        #pragma unroll
        for (int j = 0; j < 4; j++)
            #pragma unroll
            for (int q = 0; q < 4; q++) acc[i][j][q] = 0.f;

    const uint32_t aRow = lane & 15;
    const uint32_t aCol = (lane & 16) >> 1;
    const uint32_t bRow = (lane & 7) + ((lane & 16) >> 1);
    const uint32_t bCol = (lane & 8) ? 8u : 0u;

    load_stage(0, 0);
    load_stage(1, 1);

    const int NSTAGE = NF / BK;   // 16
    for (int s = 0; s < NSTAGE; s++) {
        const int buf = s % 3;
        if (s + 2 < NSTAGE) {
            load_stage(s + 2, (s + 2) % 3);
            cp_wait<2>();
        } else if (s + 1 < NSTAGE) {
            cp_wait<1>();
        } else {
            cp_wait<0>();
        }
        __syncthreads();

        const uint32_t st = sb + buf * STAGE_B;
        #pragma unroll
        for (int kk = 0; kk < 2; kk++) {
            const int k0 = kk * 16;
            uint32_t ah[4][4], bh[4][2];
            #pragma unroll
            for (int mt = 0; mt < 4; mt++) {
                uint32_t off = ((wm * 64 + mt * 16 + aRow) * TSTRIDE + k0 + aCol) * 2;
                ldsm4(ah[mt][0], ah[mt][1], ah[mt][2], ah[mt][3], st + 0 * TILE_B + off);
            }
            #pragma unroll
            for (int np = 0; np < 2; np++) {
                uint32_t off = ((wn * 32 + np * 16 + bRow) * TSTRIDE + k0 + bCol) * 2;
                ldsm4(bh[np*2][0], bh[np*2][1], bh[np*2+1][0], bh[np*2+1][1],
                      st + 1 * TILE_B + off);
            }
            #pragma unroll
            for (int mt = 0; mt < 4; mt++)
                #pragma unroll
                for (int nt = 0; nt < 4; nt++)
                    mma16816(acc[mt][nt][0], acc[mt][nt][1], acc[mt][nt][2], acc[mt][nt][3],
                             ah[mt][0], ah[mt][1], ah[mt][2], ah[mt][3], bh[nt][0], bh[nt][1]);
        }
        __syncthreads();
    }

    // ---- epilogue A: store fp16 h1 ----
    const int erow = (lane >> 2);
    const int ecol = (lane & 3) * 2;
    #pragma unroll
    for (int mt = 0; mt < 4; mt++) {
        int r0 = bm + wm * 64 + mt * 16 + erow;
        #pragma unroll
        for (int nt = 0; nt < 4; nt++) {
            int c = bn + wn * 32 + nt * 8 + ecol;
            if (r0 < NN) {
                __half2 p = __floats2half2_rn(acc[mt][nt][0], acc[mt][nt][1]);
                *(__half2*)(g_h1h + (size_t)r0 * HID1 + c) = p;
            }
            if (r0 + 8 < NN) {
                __half2 p = __floats2half2_rn(acc[mt][nt][2], acc[mt][nt][3]);
                *(__half2*)(g_h1h + (size_t)(r0 + 8) * HID1 + c) = p;
            }
        }
    }

    // ---- epilogue B: fused attention-score partial dots ----
    // all cols of this warp live in head h; feat f = (wn&1)*32 + nt*8 + ecol
    {
        const int h = (bn >> 6) + (wn >> 1);
        const int fbase = (wn & 1) * 32;
        float asv[4][2], adv[4][2];
        #pragma unroll
        for (int nt = 0; nt < 4; nt++) {
            int f = fbase + nt * 8 + ecol;
            asv[nt][0] = __ldg(&a1[h * 128 + f]);
            asv[nt][1] = __ldg(&a1[h * 128 + f + 1]);
            adv[nt][0] = __ldg(&a1[h * 128 + 64 + f]);
            adv[nt][1] = __ldg(&a1[h * 128 + 64 + f + 1]);
        }
        #pragma unroll
        for (int mt = 0; mt < 4; mt++) {
            float ps0 = 0.f, pd0 = 0.f, ps8 = 0.f, pd8 = 0.f;
            #pragma unroll
            for (int nt = 0; nt < 4; nt++) {
                ps0 += acc[mt][nt][0] * asv[nt][0] + acc[mt][nt][1] * asv[nt][1];
                pd0 += acc[mt][nt][0] * adv[nt][0] + acc[mt][nt][1] * adv[nt][1];
                ps8 += acc[mt][nt][2] * asv[nt][0] + acc[mt][nt][3] * asv[nt][1];
                pd8 += acc[mt][nt][2] * adv[nt][0] + acc[mt][nt][3] * adv[nt][1];
            }
            #pragma unroll
            for (int o = 1; o <= 2; o <<= 1) {
                ps0 += __shfl_xor_sync(0xffffffffu, ps0, o);
                pd0 += __shfl_xor_sync(0xffffffffu, pd0, o);
                ps8 += __shfl_xor_sync(0xffffffffu, ps8, o);
                pd8 += __shfl_xor_sync(0xffffffffu, pd8, o);
            }
            if ((lane & 3) == 0) {
                int r0 = bm + wm * 64 + mt * 16 + erow;
                if (r0 < NN) {
                    atomicAdd(&g_ssrc1[r0 * H1N + h], ps0);
                    atomicAdd(&g_sdst1[r0 * H1N + h], pd0);
                }
                if (r0 + 8 < NN) {
                    atomicAdd(&g_ssrc1[(r0 + 8) * H1N + h], ps8);
                    atomicAdd(&g_sdst1[(r0 + 8) * H1N + h], pd8);
                }
            }
        }
    }
}

// ---------------- layer-1 edge aggregation (CSR, staged ev, fp16 gather) ----
__global__ __launch_bounds__(128) void agg1_kernel() {
    int n = blockIdx.x;
    int t = threadIdx.x;
    int head = t >> 4;          // aggregation head (feature group)
    int evh = t & 7;            // head this thread computes ev for
    __shared__ int   sc[128];
    __shared__ float sev[128 * H1N];
    int beg = g_rowptr[n], end = g_rowptr[n + 1];
    float ssh = g_ssrc1[n * H1N + evh];
    float4 acc = make_float4(0.f, 0.f, 0.f, 0.f);
    float rsum = 0.f;
    int c0 = t * 4;
    for (int base = beg; base < end; base += 128) {
        int cnt = min(128, end - base);
        if (t < cnt) sc[t] = g_col[base + t];
        __syncthreads();
        for (int j0 = (t >> 3); j0 < cnt; j0 += 16) {
            int d = sc[j0];
            float lg = ssh + __ldg(&g_sdst1[d * H1N + evh]);
            float lr = lg > 0.f ? lg : 0.2f * lg;
            sev[j0 * H1N + evh] = __expf(-lr);
        }
        __syncthreads();
        int j = 0;
        for (; j + 4 <= cnt; j += 4) {
            int d0 = sc[j], d1 = sc[j+1], d2 = sc[j+2], d3 = sc[j+3];
            float e0 = sev[(j+0) * H1N + head];
            float e1 = sev[(j+1) * H1N + head];
            float e2 = sev[(j+2) * H1N + head];
            float e3 = sev[(j+3) * H1N + head];
            uint2 r0 = *(const uint2*)(g_h1h + (size_t)d0 * HID1 + c0);
            uint2 r1 = *(const uint2*)(g_h1h + (size_t)d1 * HID1 + c0);
            uint2 r2 = *(const uint2*)(g_h1h + (size_t)d2 * HID1 + c0);
            uint2 r3 = *(const uint2*)(g_h1h + (size_t)d3 * HID1 + c0);
            rsum += e0 + e1 + e2 + e3;
            float2 a, b;
            a = __half22float2(*(__half2*)&r0.x); b = __half22float2(*(__half2*)&r0.y);
            acc.x += e0 * a.x; acc.y += e0 * a.y; acc.z += e0 * b.x; acc.w += e0 * b.y;
            a = __half22float2(*(__half2*)&r1.x); b = __half22float2(*(__half2*)&r1.y);
            acc.x += e1 * a.x; acc.y += e1 * a.y; acc.z += e1 * b.x; acc.w += e1 * b.y;
            a = __half22float2(*(__half2*)&r2.x); b = __half22float2(*(__half2*)&r2.y);
            acc.x += e2 * a.x; acc.y += e2 * a.y; acc.z += e2 * b.x; acc.w += e2 * b.y;
            a = __half22float2(*(__half2*)&r3.x); b = __half22float2(*(__half2*)&r3.y);
            acc.x += e3 * a.x; acc.y += e3 * a.y; acc.z += e3 * b.x; acc.w += e3 * b.y;
        }
        for (; j < cnt; j++) {
            int d = sc[j];
            float ev = sev[j * H1N + head];
            rsum += ev;
            uint2 raw = *(const uint2*)(g_h1h + (size_t)d * HID1 + c0);
            float2 f01 = __half22float2(*(__half2*)&raw.x);
            float2 f23 = __half22float2(*(__half2*)&raw.y);
            acc.x += ev * f01.x; acc.y += ev * f01.y;
            acc.z += ev * f23.x; acc.w += ev * f23.y;
        }
        __syncthreads();
    }
    float inv = 1.f / rsum;
    float4 hp = make_float4(acc.x * inv, acc.y * inv, acc.z * inv, acc.w * inv);
    hp.x = hp.x > 0.f ? hp.x : (__expf(hp.x) - 1.f);
    hp.y = hp.y > 0.f ? hp.y : (__expf(hp.y) - 1.f);
    hp.z = hp.z > 0.f ? hp.z : (__expf(hp.z) - 1.f);
    hp.w = hp.w > 0.f ? hp.w : (__expf(hp.w) - 1.f);
    __half2 pa = __floats2half2_rn(hp.x, hp.y);
    __half2 pb = __floats2half2_rn(hp.z, hp.w);
    uint2 pk = make_uint2(*(uint32_t*)&pa, *(uint32_t*)&pb);
    *(uint2*)(g_hp1h + (size_t)n * HID1 + c0) = pk;
}

// ---------------- layer-2 GEMM (N=16) + scores ----------------
__global__ void l2_kernel(const float* __restrict__ W2, const float* __restrict__ a2) {
    int tid = blockIdx.x * blockDim.x + threadIdx.x;
    int n = tid >> 4, c = tid & 15;
    if (n >= NN) return;
    const __half* hrow = g_hp1h + (size_t)n * HID1;
    float acc = 0.f;
    for (int k = 0; k < HID1; k += 4) {
        uint2 raw = *(const uint2*)(hrow + k);
        float2 f01 = __half22float2(*(__half2*)&raw.x);
        float2 f23 = __half22float2(*(__half2*)&raw.y);
        acc += f01.x * W2[(k + 0) * NC + c];
        acc += f01.y * W2[(k + 1) * NC + c];
        acc += f23.x * W2[(k + 2) * NC + c];
        acc += f23.y * W2[(k + 3) * NC + c];
    }
    g_h2[n * NC + c] = acc;
    float ps = acc * a2[c], pd = acc * a2[NC + c];
    #pragma unroll
    for (int o = 8; o; o >>= 1) {
        ps += __shfl_xor_sync(0xffffffffu, ps, o, 16);
        pd += __shfl_xor_sync(0xffffffffu, pd, o, 16);
    }
    if (c == 0) { g_ss2[n] = ps; g_sd2[n] = pd; }
}

// ---------------- layer-2 aggregation + elu + log_softmax (edge-parallel) ---
__global__ void agg2_kernel(float* __restrict__ out) {
    int gw = (blockIdx.x * blockDim.x + threadIdx.x) >> 5;
    int lane = threadIdx.x & 31;
    if (gw >= NN) return;
    int n = gw;
    int beg = g_rowptr[n], end = g_rowptr[n + 1];
    float ss = g_ss2[n];
    float rsum = 0.f;
    float4 A0 = make_float4(0.f,0.f,0.f,0.f), A1 = A0, A2 = A0, A3 = A0;
    for (int e = beg + lane; e < end; e += 32) {
        int d = g_col[e];
        float lg = ss + __ldg(&g_sd2[d]);
        float lr = lg > 0.f ? lg : 0.2f * lg;
        float ev = __expf(-lr);
        rsum += ev;
        const float4* hp = (const float4*)(g_h2 + d * NC);
        float4 v0 = hp[0], v1 = hp[1], v2 = hp[2], v3 = hp[3];
        A0.x += ev*v0.x; A0.y += ev*v0.y; A0.z += ev*v0.z; A0.w += ev*v0.w;
        A1.x += ev*v1.x; A1.y += ev*v1.y; A1.z += ev*v1.z; A1.w += ev*v1.w;
        A2.x += ev*v2.x; A2.y += ev*v2.y; A2.z += ev*v2.z; A2.w += ev*v2.w;
        A3.x += ev*v3.x; A3.y += ev*v3.y; A3.z += ev*v3.z; A3.w += ev*v3.w;
    }
    #pragma unroll
    for (int o = 16; o; o >>= 1) {
        rsum += __shfl_xor_sync(0xffffffffu, rsum, o);
        A0.x += __shfl_xor_sync(0xffffffffu, A0.x, o);
        A0.y += __shfl_xor_sync(0xffffffffu, A0.y, o);
        A0.z += __shfl_xor_sync(0xffffffffu, A0.z, o);
        A0.w += __shfl_xor_sync(0xffffffffu, A0.w, o);
        A1.x += __shfl_xor_sync(0xffffffffu, A1.x, o);
        A1.y += __shfl_xor_sync(0xffffffffu, A1.y, o);
        A1.z += __shfl_xor_sync(0xffffffffu, A1.z, o);
        A1.w += __shfl_xor_sync(0xffffffffu, A1.w, o);
        A2.x += __shfl_xor_sync(0xffffffffu, A2.x, o);
        A2.y += __shfl_xor_sync(0xffffffffu, A2.y, o);
        A2.z += __shfl_xor_sync(0xffffffffu, A2.z, o);
        A2.w += __shfl_xor_sync(0xffffffffu, A2.w, o);
        A3.x += __shfl_xor_sync(0xffffffffu, A3.x, o);
        A3.y += __shfl_xor_sync(0xffffffffu, A3.y, o);
        A3.z += __shfl_xor_sync(0xffffffffu, A3.z, o);
        A3.w += __shfl_xor_sync(0xffffffffu, A3.w, o);
    }
    if (lane == 0) {
        float inv = 1.f / rsum;
        float e[16];
        e[0]=A0.x*inv; e[1]=A0.y*inv; e[2]=A0.z*inv; e[3]=A0.w*inv;
        e[4]=A1.x*inv; e[5]=A1.y*inv; e[6]=A1.z*inv; e[7]=A1.w*inv;
        e[8]=A2.x*inv; e[9]=A2.y*inv; e[10]=A2.z*inv; e[11]=A2.w*inv;
        e[12]=A3.x*inv; e[13]=A3.y*inv; e[14]=A3.z*inv; e[15]=A3.w*inv;
        float m = -1e30f;
        #pragma unroll
        for (int c = 0; c < 16; c++) {
            e[c] = e[c] > 0.f ? e[c] : (__expf(e[c]) - 1.f);   // elu
            m = fmaxf(m, e[c]);
        }
        float s = 0.f;
        #pragma unroll
        for (int c = 0; c < 16; c++) s += __expf(e[c] - m);
        float lse = m + __logf(s);
        float* o = out + (size_t)n * NC;
        *(float4*)(o + 0)  = make_float4(e[0]-lse, e[1]-lse, e[2]-lse, e[3]-lse);
        *(float4*)(o + 4)  = make_float4(e[4]-lse, e[5]-lse, e[6]-lse, e[7]-lse);
        *(float4*)(o + 8)  = make_float4(e[8]-lse, e[9]-lse, e[10]-lse, e[11]-lse);
        *(float4*)(o + 12) = make_float4(e[12]-lse, e[13]-lse, e[14]-lse, e[15]-lse);
    }
}

// ---------------- launch ----------------
extern "C" void kernel_launch(void* const* d_in, const int* in_sizes, int n_in,
                              void* d_out, int out_size) {
    const float* x  = (const float*)d_in[0];
    const int*   ei = (const int*)d_in[1];
    const float* W1 = (const float*)d_in[2];
    const float* a1 = (const float*)d_in[3];
    const float* W2 = (const float*)d_in[4];
    const float* a2 = (const float*)d_in[5];
    float* out = (float*)d_out;
    const int E = NE;
    const int* src = ei;
    const int* dst = ei + E;

    cudaFuncSetAttribute(gemm1_mma_kernel,
                         cudaFuncAttributeMaxDynamicSharedMemorySize, GEMM_SMEM);

    // zero deg + score accumulators; CSR build
    zero_kernel<<<(NN * H1N + 255) / 256, 256>>>();
    hist_kernel<<<(E + 255) / 256, 256>>>(src, E);
    scan_kernel<<<1, 1024>>>();
    scatter_kernel<<<(E + 255) / 256, 256>>>(src, dst, E);

    // bf16 conversion
    convert_x_kernel<<<(int)(((size_t)NNPAD * NF / 4 + 255) / 256), 256>>>(x);
    convert_w_kernel<<<(HID1 * NF + 255) / 256, 256>>>(W1);

    // layer 1 (GEMM + fused scores)
    dim3 g1(NNPAD / 128, 4);
    gemm1_mma_kernel<<<g1, 256, GEMM_SMEM>>>(a1);
    agg1_kernel<<<NN, 128>>>();

    // layer 2 + output
    l2_kernel<<<(NN * 16 + 255) / 256, 256>>>(W2, a2);
    agg2_kernel<<<(NN * 32 + 255) / 256, 256>>>(out);
}